// round 1
// baseline (speedup 1.0000x reference)
#include <cuda_runtime.h>
#include <cuda_bf16.h>
#include <math.h>

// Problem constants
#define Bb 2
#define Nn 2048
#define Ww 1024
#define Hh 16
#define HDd 64
#define ROWS (Bb * Nn)   // 4096

// ----------------------------------------------------------------------------
// Scratch buffers (static __device__ globals; no runtime allocation allowed)
// ----------------------------------------------------------------------------
__device__ float g_ln[ROWS * Ww];          // layernorm output (reused)
__device__ float g_qkv[ROWS * 3 * Ww];     // qkv projection output
__device__ float g_att[ROWS * Ww];         // attention output
__device__ float g_x1[ROWS * Ww];          // post-attention residual
__device__ float g_h[ROWS * 4 * Ww];       // fc (gelu) output

// ----------------------------------------------------------------------------
// LayerNorm: one block per row of 1024, 256 threads, float4 per thread
// ----------------------------------------------------------------------------
__global__ void ln_kernel(const float* __restrict__ x, const float* __restrict__ g,
                          const float* __restrict__ beta, float* __restrict__ y) {
    int row = blockIdx.x, tid = threadIdx.x;
    const float* xr = x + (size_t)row * Ww;
    float4 v = *(const float4*)(xr + tid * 4);
    float s = v.x + v.y + v.z + v.w;
    float ss = v.x * v.x + v.y * v.y + v.z * v.z + v.w * v.w;
    #pragma unroll
    for (int off = 16; off; off >>= 1) {
        s  += __shfl_xor_sync(0xffffffffu, s, off);
        ss += __shfl_xor_sync(0xffffffffu, ss, off);
    }
    __shared__ float sb[8], sq[8];
    if ((tid & 31) == 0) { sb[tid >> 5] = s; sq[tid >> 5] = ss; }
    __syncthreads();
    if (tid < 32) {
        float a  = (tid < 8) ? sb[tid] : 0.f;
        float b2 = (tid < 8) ? sq[tid] : 0.f;
        #pragma unroll
        for (int off = 4; off; off >>= 1) {
            a  += __shfl_xor_sync(0xffffffffu, a, off);
            b2 += __shfl_xor_sync(0xffffffffu, b2, off);
        }
        if (tid == 0) { sb[0] = a; sq[0] = b2; }
    }
    __syncthreads();
    float mean = sb[0] * (1.f / Ww);
    float var  = sq[0] * (1.f / Ww) - mean * mean;
    float rstd = rsqrtf(var + 1e-5f);
    float4 gv = *(const float4*)(g + tid * 4);
    float4 bv = *(const float4*)(beta + tid * 4);
    float4 o;
    o.x = (v.x - mean) * rstd * gv.x + bv.x;
    o.y = (v.y - mean) * rstd * gv.y + bv.y;
    o.z = (v.z - mean) * rstd * gv.z + bv.z;
    o.w = (v.w - mean) * rstd * gv.w + bv.w;
    *(float4*)(y + (size_t)row * Ww + tid * 4) = o;
}

// ----------------------------------------------------------------------------
// SGEMM: C[M,N] = A[M,K] @ B[K,N] (+bias) (+gelu | +residual)
// 128x128x8 tiles, 256 threads, 8x8 per thread.
// EPI: 0 = bias, 1 = bias+gelu(exact), 2 = bias+residual
// M, N divisible by 128; K divisible by 8 (guaranteed for these shapes).
// ----------------------------------------------------------------------------
__device__ __forceinline__ float gelu_exact(float v) {
    return 0.5f * v * (1.0f + erff(v * 0.70710678118654752f));
}

template <int EPI>
__global__ void __launch_bounds__(256, 2)
sgemm_kernel(const float* __restrict__ A, const float* __restrict__ B,
             const float* __restrict__ bias, const float* __restrict__ res,
             float* __restrict__ C, int M, int N, int K) {
    __shared__ float As[8 * 132];   // [k][m], padded row 132 (16B-aligned rows)
    __shared__ float Bs[8 * 128];   // [k][n]
    const int tid = threadIdx.x;
    const int tx = tid & 15, ty = tid >> 4;
    const int bm = blockIdx.y * 128;
    const int bn = blockIdx.x * 128;

    const int arow = tid >> 1;            // 0..127
    const int acol = (tid & 1) * 4;       // 0 or 4
    const int bkr  = tid >> 5;            // 0..7
    const int bcol = (tid & 31) * 4;      // 0..124

    const float* Aptr = A + (size_t)(bm + arow) * K + acol;
    const float* Bptr = B + (size_t)bkr * N + bn + bcol;

    float acc[8][8];
    #pragma unroll
    for (int i = 0; i < 8; i++)
        #pragma unroll
        for (int j = 0; j < 8; j++) acc[i][j] = 0.f;

    for (int k0 = 0; k0 < K; k0 += 8) {
        float4 a = *(const float4*)Aptr;  Aptr += 8;
        As[(acol + 0) * 132 + arow] = a.x;
        As[(acol + 1) * 132 + arow] = a.y;
        As[(acol + 2) * 132 + arow] = a.z;
        As[(acol + 3) * 132 + arow] = a.w;
        float4 b = *(const float4*)Bptr;  Bptr += (size_t)8 * N;
        *(float4*)&Bs[bkr * 128 + bcol] = b;
        __syncthreads();
        #pragma unroll
        for (int k = 0; k < 8; k++) {
            float4 a0 = *(const float4*)&As[k * 132 + ty * 8];
            float4 a1 = *(const float4*)&As[k * 132 + ty * 8 + 4];
            float4 b0 = *(const float4*)&Bs[k * 128 + tx * 8];
            float4 b1 = *(const float4*)&Bs[k * 128 + tx * 8 + 4];
            float ar[8] = {a0.x, a0.y, a0.z, a0.w, a1.x, a1.y, a1.z, a1.w};
            float br[8] = {b0.x, b0.y, b0.z, b0.w, b1.x, b1.y, b1.z, b1.w};
            #pragma unroll
            for (int i = 0; i < 8; i++)
                #pragma unroll
                for (int j = 0; j < 8; j++)
                    acc[i][j] += ar[i] * br[j];
        }
        __syncthreads();
    }

    #pragma unroll
    for (int i = 0; i < 8; i++) {
        int row = bm + ty * 8 + i;
        #pragma unroll
        for (int j4 = 0; j4 < 8; j4 += 4) {
            int col = bn + tx * 8 + j4;
            float4 bi = *(const float4*)(bias + col);
            float4 o;
            o.x = acc[i][j4 + 0] + bi.x;
            o.y = acc[i][j4 + 1] + bi.y;
            o.z = acc[i][j4 + 2] + bi.z;
            o.w = acc[i][j4 + 3] + bi.w;
            if (EPI == 1) {
                o.x = gelu_exact(o.x); o.y = gelu_exact(o.y);
                o.z = gelu_exact(o.z); o.w = gelu_exact(o.w);
            }
            if (EPI == 2) {
                float4 rv = *(const float4*)(res + (size_t)row * N + col);
                o.x += rv.x; o.y += rv.y; o.z += rv.z; o.w += rv.w;
            }
            *(float4*)&C[(size_t)row * N + col] = o;
        }
    }
}

// ----------------------------------------------------------------------------
// Flash attention (fp32, online softmax).
// qkv layout: [b*N + t][h*192 + {0..63 q | 64..127 k | 128..191 v}]
// Block: 256 threads, 64 queries x full head; loops over 64-key tiles.
// Thread tile: 4x4 (16x16 thread grid).
// smem: Qs d-major [64][68], Ks d-major [64][68], Vs c-major [64][68],
//       Ps [64][65] (P transposed: [key][query]).
// ----------------------------------------------------------------------------
#define FA_SMEM ((3 * 64 * 68 + 64 * 65) * 4)

__global__ void __launch_bounds__(256, 2)
flash_kernel(const float* __restrict__ qkv, float* __restrict__ out) {
    extern __shared__ float sm[];
    float* Qs = sm;                  // [d][q] stride 68
    float* Ks = Qs + 64 * 68;        // [d][c] stride 68
    float* Vs = Ks + 64 * 68;        // [c][d] stride 68
    float* Ps = Vs + 64 * 68;        // [c][r] stride 65

    const int tid = threadIdx.x;
    const int tx = tid & 15, ty = tid >> 4;
    const int qt = blockIdx.x, h = blockIdx.y, b = blockIdx.z;

    const float* qbase = qkv + (size_t)b * Nn * (3 * Ww) + h * 192;
    const float* kbase = qbase + 64;
    const float* vbase = qbase + 128;

    // Load Q tile, fold scale^2 = 1/8 into Q
    #pragma unroll
    for (int it = 0; it < 4; it++) {
        int idx = it * 256 + tid;     // 0..1023
        int q = idx >> 4;             // 0..63
        int d4 = (idx & 15) * 4;      // 0..60
        float4 v = *(const float4*)(qbase + (size_t)(qt * 64 + q) * (3 * Ww) + d4);
        Qs[(d4 + 0) * 68 + q] = v.x * 0.125f;
        Qs[(d4 + 1) * 68 + q] = v.y * 0.125f;
        Qs[(d4 + 2) * 68 + q] = v.z * 0.125f;
        Qs[(d4 + 3) * 68 + q] = v.w * 0.125f;
    }

    float mrow[4], lrow[4], O[4][4];
    #pragma unroll
    for (int i = 0; i < 4; i++) {
        mrow[i] = -INFINITY; lrow[i] = 0.f;
        #pragma unroll
        for (int j = 0; j < 4; j++) O[i][j] = 0.f;
    }

    for (int kt = 0; kt < Nn / 64; kt++) {
        __syncthreads();  // protect Ks/Vs/Ps from prior-iteration readers
        #pragma unroll
        for (int it = 0; it < 4; it++) {
            int idx = it * 256 + tid;
            int c = idx >> 4;
            int d4 = (idx & 15) * 4;
            size_t roff = (size_t)(kt * 64 + c) * (3 * Ww) + d4;
            float4 kv = *(const float4*)(kbase + roff);
            Ks[(d4 + 0) * 68 + c] = kv.x;
            Ks[(d4 + 1) * 68 + c] = kv.y;
            Ks[(d4 + 2) * 68 + c] = kv.z;
            Ks[(d4 + 3) * 68 + c] = kv.w;
            float4 vv = *(const float4*)(vbase + roff);
            *(float4*)&Vs[c * 68 + d4] = vv;
        }
        __syncthreads();

        // S = Q^T K  (outer-product over d)
        float S[4][4];
        #pragma unroll
        for (int i = 0; i < 4; i++)
            #pragma unroll
            for (int j = 0; j < 4; j++) S[i][j] = 0.f;
        #pragma unroll 8
        for (int d = 0; d < 64; d++) {
            float4 qv = *(const float4*)&Qs[d * 68 + ty * 4];
            float4 kv = *(const float4*)&Ks[d * 68 + tx * 4];
            float qa[4] = {qv.x, qv.y, qv.z, qv.w};
            float ka[4] = {kv.x, kv.y, kv.z, kv.w};
            #pragma unroll
            for (int i = 0; i < 4; i++)
                #pragma unroll
                for (int j = 0; j < 4; j++)
                    S[i][j] += qa[i] * ka[j];
        }

        // online softmax per row (replicated across the 16-lane tx group)
        #pragma unroll
        for (int i = 0; i < 4; i++) {
            float mx = fmaxf(fmaxf(S[i][0], S[i][1]), fmaxf(S[i][2], S[i][3]));
            #pragma unroll
            for (int off = 8; off; off >>= 1)
                mx = fmaxf(mx, __shfl_xor_sync(0xffffffffu, mx, off));
            float nm = fmaxf(mrow[i], mx);
            float alpha = expf(mrow[i] - nm);
            float sum = 0.f;
            #pragma unroll
            for (int j = 0; j < 4; j++) { S[i][j] = expf(S[i][j] - nm); sum += S[i][j]; }
            #pragma unroll
            for (int off = 8; off; off >>= 1)
                sum += __shfl_xor_sync(0xffffffffu, sum, off);
            lrow[i] = lrow[i] * alpha + sum;
            #pragma unroll
            for (int j = 0; j < 4; j++) O[i][j] *= alpha;
            mrow[i] = nm;
            #pragma unroll
            for (int j = 0; j < 4; j++)
                Ps[(tx * 4 + j) * 65 + ty * 4 + i] = S[i][j];
        }
        __syncthreads();

        // O += P @ V
        #pragma unroll 8
        for (int c = 0; c < 64; c++) {
            float4 vv = *(const float4*)&Vs[c * 68 + tx * 4];
            float va[4] = {vv.x, vv.y, vv.z, vv.w};
            #pragma unroll
            for (int i = 0; i < 4; i++) {
                float p = Ps[c * 65 + ty * 4 + i];
                #pragma unroll
                for (int j = 0; j < 4; j++)
                    O[i][j] += p * va[j];
            }
        }
    }

    // epilogue: normalize and store out[(b*N + q)][h*64 + d]
    #pragma unroll
    for (int i = 0; i < 4; i++) {
        float inv = 1.f / lrow[i];
        int q = qt * 64 + ty * 4 + i;
        float4 o;
        o.x = O[i][0] * inv; o.y = O[i][1] * inv;
        o.z = O[i][2] * inv; o.w = O[i][3] * inv;
        *(float4*)&out[(size_t)(b * Nn + q) * Ww + h * 64 + tx * 4] = o;
    }
}

// ----------------------------------------------------------------------------
// Launcher
// ----------------------------------------------------------------------------
extern "C" void kernel_launch(void* const* d_in, const int* in_sizes, int n_in,
                              void* d_out, int out_size) {
    const float* x      = (const float*)d_in[0];
    const float* ln1_g  = (const float*)d_in[1];
    const float* ln1_b  = (const float*)d_in[2];
    const float* qkv_w  = (const float*)d_in[3];
    const float* qkv_b  = (const float*)d_in[4];
    const float* proj_w = (const float*)d_in[5];
    const float* proj_b = (const float*)d_in[6];
    const float* ln2_g  = (const float*)d_in[7];
    const float* ln2_b  = (const float*)d_in[8];
    const float* fc_w   = (const float*)d_in[9];
    const float* fc_b   = (const float*)d_in[10];
    const float* fc2_w  = (const float*)d_in[11];
    const float* fc2_b  = (const float*)d_in[12];
    float* out = (float*)d_out;

    float *t0, *qkvb, *att, *x1, *hb;
    cudaGetSymbolAddress((void**)&t0,   g_ln);
    cudaGetSymbolAddress((void**)&qkvb, g_qkv);
    cudaGetSymbolAddress((void**)&att,  g_att);
    cudaGetSymbolAddress((void**)&x1,   g_x1);
    cudaGetSymbolAddress((void**)&hb,   g_h);

    cudaFuncSetAttribute(flash_kernel, cudaFuncAttributeMaxDynamicSharedMemorySize, FA_SMEM);

    // 1. ln1(x) -> t0
    ln_kernel<<<ROWS, 256>>>(x, ln1_g, ln1_b, t0);
    // 2. qkv = t0 @ qkv_w + qkv_b   [4096, 3072]
    sgemm_kernel<0><<<dim3(3 * Ww / 128, ROWS / 128), 256>>>(t0, qkv_w, qkv_b, nullptr, qkvb, ROWS, 3 * Ww, Ww);
    // 3. attention -> att [4096, 1024]
    flash_kernel<<<dim3(Nn / 64, Hh, Bb), 256, FA_SMEM>>>(qkvb, att);
    // 4. x1 = att @ proj_w + proj_b + x
    sgemm_kernel<2><<<dim3(Ww / 128, ROWS / 128), 256>>>(att, proj_w, proj_b, x, x1, ROWS, Ww, Ww);
    // 5. ln2(x1) -> t0
    ln_kernel<<<ROWS, 256>>>(x1, ln2_g, ln2_b, t0);
    // 6. h = gelu(t0 @ fc_w + fc_b)  [4096, 4096]
    sgemm_kernel<1><<<dim3(4 * Ww / 128, ROWS / 128), 256>>>(t0, fc_w, fc_b, nullptr, hb, ROWS, 4 * Ww, Ww);
    // 7. out = h @ fc2_w + fc2_b + x1
    sgemm_kernel<2><<<dim3(Ww / 128, ROWS / 128), 256>>>(hb, fc2_w, fc2_b, x1, out, ROWS, Ww, 4 * Ww);
}

// round 3
// speedup vs baseline: 1.6747x; 1.6747x over previous
#include <cuda_runtime.h>
#include <cuda_bf16.h>
#include <math.h>
#include <stdint.h>

// Problem constants
#define Bb 2
#define Nn 2048
#define Ww 1024
#define Hh 16
#define HDd 64
#define ROWS (Bb * Nn)   // 4096

// ----------------------------------------------------------------------------
// Scratch buffers (static __device__ globals; no runtime allocation allowed)
// ----------------------------------------------------------------------------
__device__ float g_ln[ROWS * Ww];            // layernorm output (reused)
__device__ float g_qkv[ROWS * 3 * Ww];       // qkv projection output
__device__ float g_att[ROWS * Ww];           // attention output
__device__ float g_x1[ROWS * Ww];            // post-attention residual
__device__ float g_h[ROWS * 4 * Ww];         // fc (gelu) output
// bf16 hi/lo split buffers
__device__ __nv_bfloat16 g_ah[ROWS * 4 * Ww];  // A hi (max 4096x4096)
__device__ __nv_bfloat16 g_al[ROWS * 4 * Ww];  // A lo
__device__ __nv_bfloat16 g_bh[4 * Ww * Ww];    // B hi, [N,K] transposed
__device__ __nv_bfloat16 g_bl[4 * Ww * Ww];    // B lo

#define SWZ128(off) ((off) ^ (((off) >> 3) & 0x70))

__device__ __forceinline__ uint32_t smem_u32(const void* p) {
    uint32_t a;
    asm("{ .reg .u64 t; cvta.to.shared.u64 t, %1; cvt.u32.u64 %0, t; }" : "=r"(a) : "l"(p));
    return a;
}

__device__ __forceinline__ void ldsm_x4(uint32_t& a0, uint32_t& a1, uint32_t& a2, uint32_t& a3,
                                        uint32_t addr) {
    asm volatile("ldmatrix.sync.aligned.m8n8.x4.shared.b16 {%0,%1,%2,%3}, [%4];"
                 : "=r"(a0), "=r"(a1), "=r"(a2), "=r"(a3) : "r"(addr));
}
__device__ __forceinline__ void ldsm_x2(uint32_t& b0, uint32_t& b1, uint32_t addr) {
    asm volatile("ldmatrix.sync.aligned.m8n8.x2.shared.b16 {%0,%1}, [%2];"
                 : "=r"(b0), "=r"(b1) : "r"(addr));
}
__device__ __forceinline__ void mma_bf16(float& c0, float& c1, float& c2, float& c3,
                                         uint32_t a0, uint32_t a1, uint32_t a2, uint32_t a3,
                                         uint32_t b0, uint32_t b1) {
    asm volatile(
        "mma.sync.aligned.m16n8k16.row.col.f32.bf16.bf16.f32 "
        "{%0,%1,%2,%3}, {%4,%5,%6,%7}, {%8,%9}, {%0,%1,%2,%3};"
        : "+f"(c0), "+f"(c1), "+f"(c2), "+f"(c3)
        : "r"(a0), "r"(a1), "r"(a2), "r"(a3), "r"(b0), "r"(b1));
}

// ----------------------------------------------------------------------------
// Precision-split conversion kernels
// ----------------------------------------------------------------------------
__global__ void split_kernel(const float* __restrict__ in, __nv_bfloat16* __restrict__ hi,
                             __nv_bfloat16* __restrict__ lo, int n4) {
    int i = blockIdx.x * blockDim.x + threadIdx.x;
    if (i >= n4) return;
    float4 v = ((const float4*)in)[i];
    __nv_bfloat16 h0 = __float2bfloat16(v.x), h1 = __float2bfloat16(v.y);
    __nv_bfloat16 h2 = __float2bfloat16(v.z), h3 = __float2bfloat16(v.w);
    __nv_bfloat16 l0 = __float2bfloat16(v.x - __bfloat162float(h0));
    __nv_bfloat16 l1 = __float2bfloat16(v.y - __bfloat162float(h1));
    __nv_bfloat16 l2 = __float2bfloat16(v.z - __bfloat162float(h2));
    __nv_bfloat16 l3 = __float2bfloat16(v.w - __bfloat162float(h3));
    __nv_bfloat162 hh0 = __nv_bfloat162(h0, h1), hh1 = __nv_bfloat162(h2, h3);
    __nv_bfloat162 ll0 = __nv_bfloat162(l0, l1), ll1 = __nv_bfloat162(l2, l3);
    uint2 hv = make_uint2(*(uint32_t*)&hh0, *(uint32_t*)&hh1);
    uint2 lv = make_uint2(*(uint32_t*)&ll0, *(uint32_t*)&ll1);
    ((uint2*)hi)[i] = hv;
    ((uint2*)lo)[i] = lv;
}

// transpose-split: W fp32 [K,N] -> hi/lo bf16 [N,K]
__global__ void splitT_kernel(const float* __restrict__ w, __nv_bfloat16* __restrict__ hi,
                              __nv_bfloat16* __restrict__ lo, int K, int N) {
    __shared__ float t[32][33];
    int n0 = blockIdx.x * 32, k0 = blockIdx.y * 32;
    int tx = threadIdx.x, ty = threadIdx.y;   // 32 x 8
    #pragma unroll
    for (int i = 0; i < 32; i += 8)
        t[ty + i][tx] = w[(size_t)(k0 + ty + i) * N + n0 + tx];
    __syncthreads();
    #pragma unroll
    for (int i = 0; i < 32; i += 8) {
        float v = t[tx][ty + i];
        __nv_bfloat16 h = __float2bfloat16(v);
        __nv_bfloat16 l = __float2bfloat16(v - __bfloat162float(h));
        size_t o = (size_t)(n0 + ty + i) * K + k0 + tx;
        hi[o] = h;
        lo[o] = l;
    }
}

// ----------------------------------------------------------------------------
// mma.sync bf16 GEMM with hi/lo split (3 passes).
// C[M,N] = A[M,K] @ B^T (B stored [N,K]), fp32 out.
// CTA 128x128, K chunk 64, 8 warps (2x4), warp tile 64x32.
// EPI: 0 = bias, 1 = bias+gelu, 2 = bias+residual
// ----------------------------------------------------------------------------
__device__ __forceinline__ float gelu_exact(float v) {
    return 0.5f * v * (1.0f + erff(v * 0.70710678118654752f));
}

#define SM_AH 0
#define SM_AL 16384
#define SM_BH 32768
#define SM_BL 49152
#define SM_TOTAL 65536

template <int EPI>
__global__ void __launch_bounds__(256)
tc_gemm(const __nv_bfloat16* __restrict__ Ah, const __nv_bfloat16* __restrict__ Al,
        const __nv_bfloat16* __restrict__ Bh, const __nv_bfloat16* __restrict__ Bl,
        const float* __restrict__ bias, const float* __restrict__ res,
        float* __restrict__ C, int M, int N, int K) {
    extern __shared__ char smem[];
    uint32_t sb = smem_u32(smem);
    const int tid = threadIdx.x, wid = tid >> 5, lid = tid & 31;
    const int bm = blockIdx.y * 128, bn = blockIdx.x * 128;
    const int wm = (wid & 1) * 64;         // warp row offset in tile
    const int wn = (wid >> 1) * 32;        // warp col offset in tile

    float acc[4][4][4];
    #pragma unroll
    for (int i = 0; i < 4; i++)
        #pragma unroll
        for (int j = 0; j < 4; j++)
            #pragma unroll
            for (int r = 0; r < 4; r++) acc[i][j][r] = 0.f;

    // ldmatrix per-thread row components
    const int a_r  = lid & 15;             // row within 16-row A tile
    const int a_kb = (lid >> 4) * 16;      // 0 or 16 bytes (k halves)
    const int b_r  = lid & 7;              // row within 8-row B tile
    const int b_kb = ((lid >> 3) & 1) * 16;

    const int nchunk = K >> 6;
    for (int ck = 0; ck < nchunk; ck++) {
        const int k0 = ck << 6;
        if (ck) __syncthreads();
        // load 4 tiles: 128 rows x 128 bytes, SW128 swizzle
        #pragma unroll
        for (int i = 0; i < 4; i++) {
            int idx = i * 256 + tid;
            int r = idx >> 3, c = (idx & 7) * 16;
            uint32_t so = SWZ128(r * 128 + c);
            *(uint4*)(smem + SM_AH + so) =
                *(const uint4*)((const char*)(Ah + (size_t)(bm + r) * K + k0) + c);
            *(uint4*)(smem + SM_AL + so) =
                *(const uint4*)((const char*)(Al + (size_t)(bm + r) * K + k0) + c);
            *(uint4*)(smem + SM_BH + so) =
                *(const uint4*)((const char*)(Bh + (size_t)(bn + r) * K + k0) + c);
            *(uint4*)(smem + SM_BL + so) =
                *(const uint4*)((const char*)(Bl + (size_t)(bn + r) * K + k0) + c);
        }
        __syncthreads();

        #pragma unroll
        for (int pass = 0; pass < 3; pass++) {
            const uint32_t sA = sb + ((pass == 2) ? SM_AL : SM_AH);
            const uint32_t sB = sb + ((pass == 1) ? SM_BL : SM_BH);
            #pragma unroll
            for (int ks = 0; ks < 4; ks++) {
                uint32_t a[4][4], b[4][2];
                #pragma unroll
                for (int i = 0; i < 4; i++) {
                    uint32_t off = SWZ128((wm + i * 16 + a_r) * 128 + ks * 32 + a_kb);
                    ldsm_x4(a[i][0], a[i][1], a[i][2], a[i][3], sA + off);
                }
                #pragma unroll
                for (int j = 0; j < 4; j++) {
                    uint32_t off = SWZ128((wn + j * 8 + b_r) * 128 + ks * 32 + b_kb);
                    ldsm_x2(b[j][0], b[j][1], sB + off);
                }
                #pragma unroll
                for (int i = 0; i < 4; i++)
                    #pragma unroll
                    for (int j = 0; j < 4; j++)
                        mma_bf16(acc[i][j][0], acc[i][j][1], acc[i][j][2], acc[i][j][3],
                                 a[i][0], a[i][1], a[i][2], a[i][3], b[j][0], b[j][1]);
            }
        }
    }

    // epilogue: direct global stores, float2 per (i,j) per row half
    const int er = lid >> 2;          // 0..7
    const int ec = (lid & 3) * 2;     // 0,2,4,6
    #pragma unroll
    for (int i = 0; i < 4; i++) {
        #pragma unroll
        for (int j = 0; j < 4; j++) {
            int col = bn + wn + j * 8 + ec;
            float2 bi = *(const float2*)(bias + col);
            #pragma unroll
            for (int half = 0; half < 2; half++) {
                int row = bm + wm + i * 16 + er + half * 8;
                float2 o;
                o.x = acc[i][j][half * 2 + 0] + bi.x;
                o.y = acc[i][j][half * 2 + 1] + bi.y;
                if (EPI == 1) { o.x = gelu_exact(o.x); o.y = gelu_exact(o.y); }
                if (EPI == 2) {
                    float2 rv = *(const float2*)(res + (size_t)row * N + col);
                    o.x += rv.x; o.y += rv.y;
                }
                *(float2*)(C + (size_t)row * N + col) = o;
            }
        }
    }
}

// ----------------------------------------------------------------------------
// LayerNorm: one block per row of 1024, 256 threads, float4 per thread
// ----------------------------------------------------------------------------
__global__ void ln_kernel(const float* __restrict__ x, const float* __restrict__ g,
                          const float* __restrict__ beta, float* __restrict__ y) {
    int row = blockIdx.x, tid = threadIdx.x;
    const float* xr = x + (size_t)row * Ww;
    float4 v = *(const float4*)(xr + tid * 4);
    float s = v.x + v.y + v.z + v.w;
    float ss = v.x * v.x + v.y * v.y + v.z * v.z + v.w * v.w;
    #pragma unroll
    for (int off = 16; off; off >>= 1) {
        s  += __shfl_xor_sync(0xffffffffu, s, off);
        ss += __shfl_xor_sync(0xffffffffu, ss, off);
    }
    __shared__ float sb[8], sq[8];
    if ((tid & 31) == 0) { sb[tid >> 5] = s; sq[tid >> 5] = ss; }
    __syncthreads();
    if (tid < 32) {
        float a  = (tid < 8) ? sb[tid] : 0.f;
        float b2 = (tid < 8) ? sq[tid] : 0.f;
        #pragma unroll
        for (int off = 4; off; off >>= 1) {
            a  += __shfl_xor_sync(0xffffffffu, a, off);
            b2 += __shfl_xor_sync(0xffffffffu, b2, off);
        }
        if (tid == 0) { sb[0] = a; sq[0] = b2; }
    }
    __syncthreads();
    float mean = sb[0] * (1.f / Ww);
    float var  = sq[0] * (1.f / Ww) - mean * mean;
    float rstd = rsqrtf(var + 1e-5f);
    float4 gv = *(const float4*)(g + tid * 4);
    float4 bv = *(const float4*)(beta + tid * 4);
    float4 o;
    o.x = (v.x - mean) * rstd * gv.x + bv.x;
    o.y = (v.y - mean) * rstd * gv.y + bv.y;
    o.z = (v.z - mean) * rstd * gv.z + bv.z;
    o.w = (v.w - mean) * rstd * gv.w + bv.w;
    *(float4*)(y + (size_t)row * Ww + tid * 4) = o;
}

// ----------------------------------------------------------------------------
// Flash attention (fp32, online softmax). Unchanged.
// ----------------------------------------------------------------------------
#define FA_SMEM ((3 * 64 * 68 + 64 * 65) * 4)

__global__ void __launch_bounds__(256, 2)
flash_kernel(const float* __restrict__ qkv, float* __restrict__ out) {
    extern __shared__ float sm[];
    float* Qs = sm;                  // [d][q] stride 68
    float* Ks = Qs + 64 * 68;        // [d][c] stride 68
    float* Vs = Ks + 64 * 68;        // [c][d] stride 68
    float* Ps = Vs + 64 * 68;        // [c][r] stride 65

    const int tid = threadIdx.x;
    const int tx = tid & 15, ty = tid >> 4;
    const int qt = blockIdx.x, h = blockIdx.y, b = blockIdx.z;

    const float* qbase = qkv + (size_t)b * Nn * (3 * Ww) + h * 192;
    const float* kbase = qbase + 64;
    const float* vbase = qbase + 128;

    #pragma unroll
    for (int it = 0; it < 4; it++) {
        int idx = it * 256 + tid;
        int q = idx >> 4;
        int d4 = (idx & 15) * 4;
        float4 v = *(const float4*)(qbase + (size_t)(qt * 64 + q) * (3 * Ww) + d4);
        Qs[(d4 + 0) * 68 + q] = v.x * 0.125f;
        Qs[(d4 + 1) * 68 + q] = v.y * 0.125f;
        Qs[(d4 + 2) * 68 + q] = v.z * 0.125f;
        Qs[(d4 + 3) * 68 + q] = v.w * 0.125f;
    }

    float mrow[4], lrow[4], O[4][4];
    #pragma unroll
    for (int i = 0; i < 4; i++) {
        mrow[i] = -INFINITY; lrow[i] = 0.f;
        #pragma unroll
        for (int j = 0; j < 4; j++) O[i][j] = 0.f;
    }

    for (int kt = 0; kt < Nn / 64; kt++) {
        __syncthreads();
        #pragma unroll
        for (int it = 0; it < 4; it++) {
            int idx = it * 256 + tid;
            int c = idx >> 4;
            int d4 = (idx & 15) * 4;
            size_t roff = (size_t)(kt * 64 + c) * (3 * Ww) + d4;
            float4 kv = *(const float4*)(kbase + roff);
            Ks[(d4 + 0) * 68 + c] = kv.x;
            Ks[(d4 + 1) * 68 + c] = kv.y;
            Ks[(d4 + 2) * 68 + c] = kv.z;
            Ks[(d4 + 3) * 68 + c] = kv.w;
            float4 vv = *(const float4*)(vbase + roff);
            *(float4*)&Vs[c * 68 + d4] = vv;
        }
        __syncthreads();

        float S[4][4];
        #pragma unroll
        for (int i = 0; i < 4; i++)
            #pragma unroll
            for (int j = 0; j < 4; j++) S[i][j] = 0.f;
        #pragma unroll 8
        for (int d = 0; d < 64; d++) {
            float4 qv = *(const float4*)&Qs[d * 68 + ty * 4];
            float4 kv = *(const float4*)&Ks[d * 68 + tx * 4];
            float qa[4] = {qv.x, qv.y, qv.z, qv.w};
            float ka[4] = {kv.x, kv.y, kv.z, kv.w};
            #pragma unroll
            for (int i = 0; i < 4; i++)
                #pragma unroll
                for (int j = 0; j < 4; j++)
                    S[i][j] += qa[i] * ka[j];
        }

        #pragma unroll
        for (int i = 0; i < 4; i++) {
            float mx = fmaxf(fmaxf(S[i][0], S[i][1]), fmaxf(S[i][2], S[i][3]));
            #pragma unroll
            for (int off = 8; off; off >>= 1)
                mx = fmaxf(mx, __shfl_xor_sync(0xffffffffu, mx, off));
            float nm = fmaxf(mrow[i], mx);
            float alpha = expf(mrow[i] - nm);
            float sum = 0.f;
            #pragma unroll
            for (int j = 0; j < 4; j++) { S[i][j] = expf(S[i][j] - nm); sum += S[i][j]; }
            #pragma unroll
            for (int off = 8; off; off >>= 1)
                sum += __shfl_xor_sync(0xffffffffu, sum, off);
            lrow[i] = lrow[i] * alpha + sum;
            #pragma unroll
            for (int j = 0; j < 4; j++) O[i][j] *= alpha;
            mrow[i] = nm;
            #pragma unroll
            for (int j = 0; j < 4; j++)
                Ps[(tx * 4 + j) * 65 + ty * 4 + i] = S[i][j];
        }
        __syncthreads();

        #pragma unroll 8
        for (int c = 0; c < 64; c++) {
            float4 vv = *(const float4*)&Vs[c * 68 + tx * 4];
            float va[4] = {vv.x, vv.y, vv.z, vv.w};
            #pragma unroll
            for (int i = 0; i < 4; i++) {
                float p = Ps[c * 65 + ty * 4 + i];
                #pragma unroll
                for (int j = 0; j < 4; j++)
                    O[i][j] += p * va[j];
            }
        }
    }

    #pragma unroll
    for (int i = 0; i < 4; i++) {
        float inv = 1.f / lrow[i];
        int q = qt * 64 + ty * 4 + i;
        float4 o;
        o.x = O[i][0] * inv; o.y = O[i][1] * inv;
        o.z = O[i][2] * inv; o.w = O[i][3] * inv;
        *(float4*)&out[(size_t)(b * Nn + q) * Ww + h * 64 + tx * 4] = o;
    }
}

// ----------------------------------------------------------------------------
// Launcher
// ----------------------------------------------------------------------------
extern "C" void kernel_launch(void* const* d_in, const int* in_sizes, int n_in,
                              void* d_out, int out_size) {
    const float* x      = (const float*)d_in[0];
    const float* ln1_g  = (const float*)d_in[1];
    const float* ln1_b  = (const float*)d_in[2];
    const float* qkv_w  = (const float*)d_in[3];
    const float* qkv_b  = (const float*)d_in[4];
    const float* proj_w = (const float*)d_in[5];
    const float* proj_b = (const float*)d_in[6];
    const float* ln2_g  = (const float*)d_in[7];
    const float* ln2_b  = (const float*)d_in[8];
    const float* fc_w   = (const float*)d_in[9];
    const float* fc_b   = (const float*)d_in[10];
    const float* fc2_w  = (const float*)d_in[11];
    const float* fc2_b  = (const float*)d_in[12];
    float* out = (float*)d_out;

    float *t0, *qkvb, *att, *x1, *hb;
    __nv_bfloat16 *ah, *al, *bh, *bl;
    cudaGetSymbolAddress((void**)&t0,   g_ln);
    cudaGetSymbolAddress((void**)&qkvb, g_qkv);
    cudaGetSymbolAddress((void**)&att,  g_att);
    cudaGetSymbolAddress((void**)&x1,   g_x1);
    cudaGetSymbolAddress((void**)&hb,   g_h);
    cudaGetSymbolAddress((void**)&ah,   g_ah);
    cudaGetSymbolAddress((void**)&al,   g_al);
    cudaGetSymbolAddress((void**)&bh,   g_bh);
    cudaGetSymbolAddress((void**)&bl,   g_bl);

    cudaFuncSetAttribute(flash_kernel, cudaFuncAttributeMaxDynamicSharedMemorySize, FA_SMEM);
    cudaFuncSetAttribute(tc_gemm<0>, cudaFuncAttributeMaxDynamicSharedMemorySize, SM_TOTAL);
    cudaFuncSetAttribute(tc_gemm<1>, cudaFuncAttributeMaxDynamicSharedMemorySize, SM_TOTAL);
    cudaFuncSetAttribute(tc_gemm<2>, cudaFuncAttributeMaxDynamicSharedMemorySize, SM_TOTAL);

    // 1. ln1(x) -> t0
    ln_kernel<<<ROWS, 256>>>(x, ln1_g, ln1_b, t0);
    // 2. qkv = t0 @ qkv_w + qkv_b   [4096, 3072]
    split_kernel<<<ROWS * Ww / 4 / 256, 256>>>(t0, ah, al, ROWS * Ww / 4);
    splitT_kernel<<<dim3(3 * Ww / 32, Ww / 32), dim3(32, 8)>>>(qkv_w, bh, bl, Ww, 3 * Ww);
    tc_gemm<0><<<dim3(3 * Ww / 128, ROWS / 128), 256, SM_TOTAL>>>(ah, al, bh, bl, qkv_b, nullptr, qkvb, ROWS, 3 * Ww, Ww);
    // 3. attention -> att [4096, 1024]
    flash_kernel<<<dim3(Nn / 64, Hh, Bb), 256, FA_SMEM>>>(qkvb, att);
    // 4. x1 = att @ proj_w + proj_b + x
    split_kernel<<<ROWS * Ww / 4 / 256, 256>>>(att, ah, al, ROWS * Ww / 4);
    splitT_kernel<<<dim3(Ww / 32, Ww / 32), dim3(32, 8)>>>(proj_w, bh, bl, Ww, Ww);
    tc_gemm<2><<<dim3(Ww / 128, ROWS / 128), 256, SM_TOTAL>>>(ah, al, bh, bl, proj_b, x, x1, ROWS, Ww, Ww);
    // 5. ln2(x1) -> t0
    ln_kernel<<<ROWS, 256>>>(x1, ln2_g, ln2_b, t0);
    // 6. h = gelu(t0 @ fc_w + fc_b)  [4096, 4096]
    split_kernel<<<ROWS * Ww / 4 / 256, 256>>>(t0, ah, al, ROWS * Ww / 4);
    splitT_kernel<<<dim3(4 * Ww / 32, Ww / 32), dim3(32, 8)>>>(fc_w, bh, bl, Ww, 4 * Ww);
    tc_gemm<1><<<dim3(4 * Ww / 128, ROWS / 128), 256, SM_TOTAL>>>(ah, al, bh, bl, fc_b, nullptr, hb, ROWS, 4 * Ww, Ww);
    // 7. out = h @ fc2_w + fc2_b + x1
    split_kernel<<<ROWS * 4 * Ww / 4 / 256, 256>>>(hb, ah, al, ROWS * 4 * Ww / 4);
    splitT_kernel<<<dim3(Ww / 32, 4 * Ww / 32), dim3(32, 8)>>>(fc2_w, bh, bl, 4 * Ww, Ww);
    tc_gemm<2><<<dim3(Ww / 128, ROWS / 128), 256, SM_TOTAL>>>(ah, al, bh, bl, fc2_b, x1, out, ROWS, Ww, 4 * Ww);
}

// round 4
// speedup vs baseline: 3.0009x; 1.7919x over previous
#include <cuda_runtime.h>
#include <cuda_bf16.h>
#include <math.h>
#include <stdint.h>

// Problem constants
#define Bb 2
#define Nn 2048
#define Ww 1024
#define Hh 16
#define HDd 64
#define ROWS (Bb * Nn)   // 4096

// ----------------------------------------------------------------------------
// Scratch buffers (static __device__ globals; no runtime allocation allowed)
// ----------------------------------------------------------------------------
__device__ float g_x1[ROWS * Ww];                 // post-attention residual (fp32)
__device__ __nv_bfloat16 g_ah[ROWS * Ww];         // ln output hi
__device__ __nv_bfloat16 g_al[ROWS * Ww];         // ln output lo
__device__ __nv_bfloat16 g_qh[ROWS * 3 * Ww];     // qkv hi (q pre-scaled)
__device__ __nv_bfloat16 g_ql[ROWS * 3 * Ww];     // qkv lo
__device__ __nv_bfloat16 g_ath[ROWS * Ww];        // attention out hi
__device__ __nv_bfloat16 g_atl[ROWS * Ww];        // attention out lo
__device__ __nv_bfloat16 g_hh[ROWS * 4 * Ww];     // gelu out hi
__device__ __nv_bfloat16 g_hl[ROWS * 4 * Ww];     // gelu out lo
__device__ __nv_bfloat16 g_bh[4 * Ww * Ww];       // weight hi, [N,K]
__device__ __nv_bfloat16 g_bl[4 * Ww * Ww];       // weight lo, [N,K]

#define SWZ128(off) ((off) ^ (((off) >> 3) & 0x70))

__device__ __forceinline__ uint32_t smem_u32(const void* p) {
    uint32_t a;
    asm("{ .reg .u64 t; cvta.to.shared.u64 t, %1; cvt.u32.u64 %0, t; }" : "=r"(a) : "l"(p));
    return a;
}
__device__ __forceinline__ void cp16(uint32_t saddr, const void* g) {
    asm volatile("cp.async.cg.shared.global [%0], [%1], 16;" :: "r"(saddr), "l"(g));
}
#define CP_COMMIT() asm volatile("cp.async.commit_group;" ::: "memory")
#define CP_WAIT1()  asm volatile("cp.async.wait_group 1;" ::: "memory")
#define CP_WAIT0()  asm volatile("cp.async.wait_group 0;" ::: "memory")

__device__ __forceinline__ void ldsm_x4(uint32_t& a0, uint32_t& a1, uint32_t& a2, uint32_t& a3,
                                        uint32_t addr) {
    asm volatile("ldmatrix.sync.aligned.m8n8.x4.shared.b16 {%0,%1,%2,%3}, [%4];"
                 : "=r"(a0), "=r"(a1), "=r"(a2), "=r"(a3) : "r"(addr));
}
__device__ __forceinline__ void ldsm_x2(uint32_t& b0, uint32_t& b1, uint32_t addr) {
    asm volatile("ldmatrix.sync.aligned.m8n8.x2.shared.b16 {%0,%1}, [%2];"
                 : "=r"(b0), "=r"(b1) : "r"(addr));
}
__device__ __forceinline__ void ldsm_x2t(uint32_t& b0, uint32_t& b1, uint32_t addr) {
    asm volatile("ldmatrix.sync.aligned.m8n8.x2.trans.shared.b16 {%0,%1}, [%2];"
                 : "=r"(b0), "=r"(b1) : "r"(addr));
}
__device__ __forceinline__ void mma_bf16(float* c,
                                         uint32_t a0, uint32_t a1, uint32_t a2, uint32_t a3,
                                         uint32_t b0, uint32_t b1) {
    asm volatile(
        "mma.sync.aligned.m16n8k16.row.col.f32.bf16.bf16.f32 "
        "{%0,%1,%2,%3}, {%4,%5,%6,%7}, {%8,%9}, {%0,%1,%2,%3};"
        : "+f"(c[0]), "+f"(c[1]), "+f"(c[2]), "+f"(c[3])
        : "r"(a0), "r"(a1), "r"(a2), "r"(a3), "r"(b0), "r"(b1));
}
__device__ __forceinline__ uint32_t pack_bf16(float a, float b) {
    __nv_bfloat162 t = __floats2bfloat162_rn(a, b);
    return *(uint32_t*)&t;
}
__device__ __forceinline__ float gelu_exact(float v) {
    return 0.5f * v * (1.0f + erff(v * 0.70710678118654752f));
}

// ----------------------------------------------------------------------------
// transpose-split: W fp32 [K,N] -> hi/lo bf16 [N,K]
// ----------------------------------------------------------------------------
__global__ void splitT_kernel(const float* __restrict__ w, __nv_bfloat16* __restrict__ hi,
                              __nv_bfloat16* __restrict__ lo, int K, int N) {
    __shared__ float t[32][33];
    int n0 = blockIdx.x * 32, k0 = blockIdx.y * 32;
    int tx = threadIdx.x, ty = threadIdx.y;   // 32 x 8
    #pragma unroll
    for (int i = 0; i < 32; i += 8)
        t[ty + i][tx] = w[(size_t)(k0 + ty + i) * N + n0 + tx];
    __syncthreads();
    #pragma unroll
    for (int i = 0; i < 32; i += 8) {
        float v = t[tx][ty + i];
        __nv_bfloat16 h = __float2bfloat16(v);
        __nv_bfloat16 l = __float2bfloat16(v - __bfloat162float(h));
        size_t o = (size_t)(n0 + ty + i) * K + k0 + tx;
        hi[o] = h;
        lo[o] = l;
    }
}

// ----------------------------------------------------------------------------
// cp.async double-buffered mma.sync bf16 GEMM with hi/lo split (3 passes).
// ----------------------------------------------------------------------------
#define GS_AH 0
#define GS_AL 16384
#define GS_BH 32768
#define GS_BL 49152
#define GS_STAGE 65536
#define GS_TOTAL (2 * GS_STAGE)

template <int EPI>
__global__ void __launch_bounds__(256)
tc_gemm(const __nv_bfloat16* __restrict__ Ah, const __nv_bfloat16* __restrict__ Al,
        const __nv_bfloat16* __restrict__ Bh, const __nv_bfloat16* __restrict__ Bl,
        const float* __restrict__ bias, const float* __restrict__ res,
        float* __restrict__ Cf, __nv_bfloat16* __restrict__ Ch, __nv_bfloat16* __restrict__ Cl,
        int M, int N, int K) {
    extern __shared__ char smem[];
    uint32_t sb = smem_u32(smem);
    const int tid = threadIdx.x, wid = tid >> 5, lid = tid & 31;
    const int bm = blockIdx.y * 128, bn = blockIdx.x * 128;
    const int wm = (wid & 1) * 64;
    const int wn = (wid >> 1) * 32;

    float acc[4][4][4];
    #pragma unroll
    for (int i = 0; i < 4; i++)
        #pragma unroll
        for (int j = 0; j < 4; j++)
            #pragma unroll
            for (int r = 0; r < 4; r++) acc[i][j][r] = 0.f;

    const int a_r  = lid & 15;
    const int a_kb = (lid >> 4) * 16;
    const int b_r  = lid & 7;
    const int b_kb = ((lid >> 3) & 1) * 16;

    const int nchunk = K >> 6;
    #define G_LOAD(ck, s) do { \
        const int _k0 = (ck) << 6; \
        uint32_t _dst = sb + (s) * GS_STAGE; \
        _Pragma("unroll") \
        for (int _i = 0; _i < 4; _i++) { \
            int _idx = _i * 256 + tid; \
            int _r = _idx >> 3, _c = (_idx & 7) * 16; \
            uint32_t _so = SWZ128(_r * 128 + _c); \
            cp16(_dst + GS_AH + _so, (const char*)(Ah + (size_t)(bm + _r) * K + _k0) + _c); \
            cp16(_dst + GS_AL + _so, (const char*)(Al + (size_t)(bm + _r) * K + _k0) + _c); \
            cp16(_dst + GS_BH + _so, (const char*)(Bh + (size_t)(bn + _r) * K + _k0) + _c); \
            cp16(_dst + GS_BL + _so, (const char*)(Bl + (size_t)(bn + _r) * K + _k0) + _c); \
        } \
        CP_COMMIT(); \
    } while (0)

    G_LOAD(0, 0);
    for (int ck = 0; ck < nchunk; ck++) {
        if (ck + 1 < nchunk) { G_LOAD(ck + 1, (ck + 1) & 1); CP_WAIT1(); }
        else CP_WAIT0();
        __syncthreads();
        uint32_t stg = sb + (ck & 1) * GS_STAGE;
        #pragma unroll
        for (int pass = 0; pass < 3; pass++) {
            const uint32_t sA = stg + ((pass == 2) ? GS_AL : GS_AH);
            const uint32_t sB = stg + ((pass == 1) ? GS_BL : GS_BH);
            #pragma unroll
            for (int ks = 0; ks < 4; ks++) {
                uint32_t a[4][4], b[4][2];
                #pragma unroll
                for (int i = 0; i < 4; i++) {
                    uint32_t off = SWZ128((wm + i * 16 + a_r) * 128 + ks * 32 + a_kb);
                    ldsm_x4(a[i][0], a[i][1], a[i][2], a[i][3], sA + off);
                }
                #pragma unroll
                for (int j = 0; j < 4; j++) {
                    uint32_t off = SWZ128((wn + j * 8 + b_r) * 128 + ks * 32 + b_kb);
                    ldsm_x2(b[j][0], b[j][1], sB + off);
                }
                #pragma unroll
                for (int i = 0; i < 4; i++)
                    #pragma unroll
                    for (int j = 0; j < 4; j++)
                        mma_bf16(acc[i][j], a[i][0], a[i][1], a[i][2], a[i][3], b[j][0], b[j][1]);
            }
        }
        __syncthreads();
    }
    #undef G_LOAD

    const int er = lid >> 2;
    const int ec = (lid & 3) * 2;
    #pragma unroll
    for (int i = 0; i < 4; i++) {
        #pragma unroll
        for (int j = 0; j < 4; j++) {
            int col = bn + wn + j * 8 + ec;
            float2 bi = *(const float2*)(bias + col);
            #pragma unroll
            for (int half = 0; half < 2; half++) {
                int row = bm + wm + i * 16 + er + half * 8;
                float ox = acc[i][j][half * 2 + 0] + bi.x;
                float oy = acc[i][j][half * 2 + 1] + bi.y;
                if (EPI == 2) {
                    float2 rv = *(const float2*)(res + (size_t)row * N + col);
                    float2 o = make_float2(ox + rv.x, oy + rv.y);
                    *(float2*)(Cf + (size_t)row * N + col) = o;
                } else {
                    if (EPI == 3) {
                        float s = ((col % 192) < 64) ? 0.125f : 1.0f;
                        ox *= s; oy *= s;
                    }
                    if (EPI == 4) { ox = gelu_exact(ox); oy = gelu_exact(oy); }
                    __nv_bfloat16 hx = __float2bfloat16(ox), hy = __float2bfloat16(oy);
                    float lx = ox - __bfloat162float(hx), ly = oy - __bfloat162float(hy);
                    *(uint32_t*)(Ch + (size_t)row * N + col) =
                        pack_bf16(__bfloat162float(hx), __bfloat162float(hy));
                    *(uint32_t*)(Cl + (size_t)row * N + col) = pack_bf16(lx, ly);
                }
            }
        }
    }
}

// ----------------------------------------------------------------------------
// LayerNorm -> hi/lo bf16 outputs
// ----------------------------------------------------------------------------
__global__ void ln_kernel(const float* __restrict__ x, const float* __restrict__ g,
                          const float* __restrict__ beta,
                          __nv_bfloat16* __restrict__ yh, __nv_bfloat16* __restrict__ yl) {
    int row = blockIdx.x, tid = threadIdx.x;
    const float* xr = x + (size_t)row * Ww;
    float4 v = *(const float4*)(xr + tid * 4);
    float s = v.x + v.y + v.z + v.w;
    float ss = v.x * v.x + v.y * v.y + v.z * v.z + v.w * v.w;
    #pragma unroll
    for (int off = 16; off; off >>= 1) {
        s  += __shfl_xor_sync(0xffffffffu, s, off);
        ss += __shfl_xor_sync(0xffffffffu, ss, off);
    }
    __shared__ float sb[8], sq[8];
    if ((tid & 31) == 0) { sb[tid >> 5] = s; sq[tid >> 5] = ss; }
    __syncthreads();
    if (tid < 32) {
        float a  = (tid < 8) ? sb[tid] : 0.f;
        float b2 = (tid < 8) ? sq[tid] : 0.f;
        #pragma unroll
        for (int off = 4; off; off >>= 1) {
            a  += __shfl_xor_sync(0xffffffffu, a, off);
            b2 += __shfl_xor_sync(0xffffffffu, b2, off);
        }
        if (tid == 0) { sb[0] = a; sq[0] = b2; }
    }
    __syncthreads();
    float mean = sb[0] * (1.f / Ww);
    float var  = sq[0] * (1.f / Ww) - mean * mean;
    float rstd = rsqrtf(var + 1e-5f);
    float4 gv = *(const float4*)(g + tid * 4);
    float4 bv = *(const float4*)(beta + tid * 4);
    float o0 = (v.x - mean) * rstd * gv.x + bv.x;
    float o1 = (v.y - mean) * rstd * gv.y + bv.y;
    float o2 = (v.z - mean) * rstd * gv.z + bv.z;
    float o3 = (v.w - mean) * rstd * gv.w + bv.w;
    __nv_bfloat16 h0 = __float2bfloat16(o0), h1 = __float2bfloat16(o1);
    __nv_bfloat16 h2 = __float2bfloat16(o2), h3 = __float2bfloat16(o3);
    size_t base = (size_t)row * Ww + tid * 4;
    *(uint32_t*)(yh + base)     = pack_bf16(__bfloat162float(h0), __bfloat162float(h1));
    *(uint32_t*)(yh + base + 2) = pack_bf16(__bfloat162float(h2), __bfloat162float(h3));
    *(uint32_t*)(yl + base)     = pack_bf16(o0 - __bfloat162float(h0), o1 - __bfloat162float(h1));
    *(uint32_t*)(yl + base + 2) = pack_bf16(o2 - __bfloat162float(h2), o3 - __bfloat162float(h3));
}

// ----------------------------------------------------------------------------
// Tensor-core flash attention, hi/lo bf16 (3-pass S, 3-pass P@V).
// ----------------------------------------------------------------------------
#define F_QH 0
#define F_QL 16384
#define F_ST 32768
#define F_KH 0
#define F_KL 8192
#define F_VH 16384
#define F_VL 24576
#define F_STAGE 32768
#define F_TOTAL (F_ST + 2 * F_STAGE)

__global__ void __launch_bounds__(256)
flash_tc(const __nv_bfloat16* __restrict__ qh, const __nv_bfloat16* __restrict__ ql,
         __nv_bfloat16* __restrict__ oh, __nv_bfloat16* __restrict__ ol) {
    extern __shared__ char smem[];
    uint32_t sbm = smem_u32(smem);
    const int tid = threadIdx.x, wid = tid >> 5, lid = tid & 31;
    const int qt = blockIdx.x, h = blockIdx.y, b = blockIdx.z;
    const int wm = wid * 16;

    const size_t hcol = (size_t)h * 192;

    #pragma unroll
    for (int i = 0; i < 4; i++) {
        int idx = i * 256 + tid;
        int r = idx >> 3, c = (idx & 7) * 16;
        uint32_t so = SWZ128(r * 128 + c);
        const char* gq = (const char*)(qh + (size_t)(b * Nn + qt * 128 + r) * (3 * Ww) + hcol) + c;
        const char* gl = (const char*)(ql + (size_t)(b * Nn + qt * 128 + r) * (3 * Ww) + hcol) + c;
        cp16(sbm + F_QH + so, gq);
        cp16(sbm + F_QL + so, gl);
    }
    CP_COMMIT();

    #define F_LOAD(kt, s) do { \
        uint32_t _dst = sbm + F_ST + (s) * F_STAGE; \
        _Pragma("unroll") \
        for (int _i = 0; _i < 2; _i++) { \
            int _idx = _i * 256 + tid; \
            int _r = _idx >> 3, _c = (_idx & 7) * 16; \
            uint32_t _so = SWZ128(_r * 128 + _c); \
            size_t _row = (size_t)(b * Nn + (kt) * 64 + _r) * (3 * Ww) + hcol; \
            cp16(_dst + F_KH + _so, (const char*)(qh + _row + 64) + _c); \
            cp16(_dst + F_KL + _so, (const char*)(ql + _row + 64) + _c); \
            cp16(_dst + F_VH + _so, (const char*)(qh + _row + 128) + _c); \
            cp16(_dst + F_VL + _so, (const char*)(ql + _row + 128) + _c); \
        } \
        CP_COMMIT(); \
    } while (0)

    F_LOAD(0, 0);

    const int a_r  = lid & 15;
    const int a_kb = (lid >> 4) * 16;
    const int b_r  = lid & 7;
    const int b_kb = ((lid >> 3) & 1) * 16;

    float O[8][4];
    #pragma unroll
    for (int j = 0; j < 8; j++)
        #pragma unroll
        for (int r = 0; r < 4; r++) O[j][r] = 0.f;
    float m0 = -INFINITY, m1 = -INFINITY, l0 = 0.f, l1 = 0.f;

    const int NKT = Nn / 64;
    for (int kt = 0; kt < NKT; kt++) {
        if (kt + 1 < NKT) { F_LOAD(kt + 1, (kt + 1) & 1); CP_WAIT1(); }
        else CP_WAIT0();
        __syncthreads();
        uint32_t stg = sbm + F_ST + (kt & 1) * F_STAGE;

        float S[8][4];
        #pragma unroll
        for (int j = 0; j < 8; j++)
            #pragma unroll
            for (int r = 0; r < 4; r++) S[j][r] = 0.f;
        #pragma unroll
        for (int pass = 0; pass < 3; pass++) {
            const uint32_t sA = sbm + ((pass == 2) ? F_QL : F_QH);
            const uint32_t sB = stg + ((pass == 1) ? F_KL : F_KH);
            #pragma unroll
            for (int ks = 0; ks < 4; ks++) {
                uint32_t a0, a1, a2, a3;
                ldsm_x4(a0, a1, a2, a3, sA + SWZ128((wm + a_r) * 128 + ks * 32 + a_kb));
                #pragma unroll
                for (int j = 0; j < 8; j++) {
                    uint32_t b0, b1;
                    ldsm_x2(b0, b1, sB + SWZ128((j * 8 + b_r) * 128 + ks * 32 + b_kb));
                    mma_bf16(S[j], a0, a1, a2, a3, b0, b1);
                }
            }
        }

        float mx0 = -INFINITY, mx1 = -INFINITY;
        #pragma unroll
        for (int j = 0; j < 8; j++) {
            mx0 = fmaxf(mx0, fmaxf(S[j][0], S[j][1]));
            mx1 = fmaxf(mx1, fmaxf(S[j][2], S[j][3]));
        }
        mx0 = fmaxf(mx0, __shfl_xor_sync(0xffffffffu, mx0, 1));
        mx0 = fmaxf(mx0, __shfl_xor_sync(0xffffffffu, mx0, 2));
        mx1 = fmaxf(mx1, __shfl_xor_sync(0xffffffffu, mx1, 1));
        mx1 = fmaxf(mx1, __shfl_xor_sync(0xffffffffu, mx1, 2));
        float nm0 = fmaxf(m0, mx0), nm1 = fmaxf(m1, mx1);
        float al0 = __expf(m0 - nm0), al1 = __expf(m1 - nm1);
        float s0 = 0.f, s1 = 0.f;
        #pragma unroll
        for (int j = 0; j < 8; j++) {
            S[j][0] = __expf(S[j][0] - nm0); s0 += S[j][0];
            S[j][1] = __expf(S[j][1] - nm0); s0 += S[j][1];
            S[j][2] = __expf(S[j][2] - nm1); s1 += S[j][2];
            S[j][3] = __expf(S[j][3] - nm1); s1 += S[j][3];
        }
        s0 += __shfl_xor_sync(0xffffffffu, s0, 1);
        s0 += __shfl_xor_sync(0xffffffffu, s0, 2);
        s1 += __shfl_xor_sync(0xffffffffu, s1, 1);
        s1 += __shfl_xor_sync(0xffffffffu, s1, 2);
        l0 = l0 * al0 + s0;
        l1 = l1 * al1 + s1;
        m0 = nm0; m1 = nm1;
        #pragma unroll
        for (int j = 0; j < 8; j++) {
            O[j][0] *= al0; O[j][1] *= al0;
            O[j][2] *= al1; O[j][3] *= al1;
        }

        #pragma unroll
        for (int t = 0; t < 4; t++) {
            uint32_t ph[4], pl[4];
            #pragma unroll
            for (int half = 0; half < 2; half++) {
                int j = 2 * t + half;
                float p0 = S[j][0], p1 = S[j][1], p2 = S[j][2], p3 = S[j][3];
                __nv_bfloat16 h0 = __float2bfloat16(p0), h1 = __float2bfloat16(p1);
                __nv_bfloat16 h2 = __float2bfloat16(p2), h3 = __float2bfloat16(p3);
                ph[half * 2 + 0] = pack_bf16(__bfloat162float(h0), __bfloat162float(h1));
                ph[half * 2 + 1] = pack_bf16(__bfloat162float(h2), __bfloat162float(h3));
                pl[half * 2 + 0] = pack_bf16(p0 - __bfloat162float(h0), p1 - __bfloat162float(h1));
                pl[half * 2 + 1] = pack_bf16(p2 - __bfloat162float(h2), p3 - __bfloat162float(h3));
            }
            uint32_t vaddr_row = t * 16 + (lid & 15);
            #pragma unroll
            for (int j = 0; j < 8; j++) {
                uint32_t off = SWZ128(vaddr_row * 128 + j * 16);
                uint32_t vh0, vh1, vl0, vl1;
                ldsm_x2t(vh0, vh1, stg + F_VH + off);
                ldsm_x2t(vl0, vl1, stg + F_VL + off);
                mma_bf16(O[j], ph[0], ph[1], ph[2], ph[3], vh0, vh1);
                mma_bf16(O[j], ph[0], ph[1], ph[2], ph[3], vl0, vl1);
                mma_bf16(O[j], pl[0], pl[1], pl[2], pl[3], vh0, vh1);
            }
        }
        __syncthreads();
    }
    #undef F_LOAD

    float inv0 = 1.f / l0, inv1 = 1.f / l1;
    int r0 = b * Nn + qt * 128 + wm + (lid >> 2);
    int r1 = r0 + 8;
    int cb = h * 64 + (lid & 3) * 2;
    #pragma unroll
    for (int j = 0; j < 8; j++) {
        int col = cb + j * 8;
        float o0 = O[j][0] * inv0, o1 = O[j][1] * inv0;
        float o2 = O[j][2] * inv1, o3 = O[j][3] * inv1;
        __nv_bfloat16 h0 = __float2bfloat16(o0), h1 = __float2bfloat16(o1);
        __nv_bfloat16 h2 = __float2bfloat16(o2), h3 = __float2bfloat16(o3);
        *(uint32_t*)(oh + (size_t)r0 * Ww + col) = pack_bf16(__bfloat162float(h0), __bfloat162float(h1));
        *(uint32_t*)(oh + (size_t)r1 * Ww + col) = pack_bf16(__bfloat162float(h2), __bfloat162float(h3));
        *(uint32_t*)(ol + (size_t)r0 * Ww + col) = pack_bf16(o0 - __bfloat162float(h0), o1 - __bfloat162float(h1));
        *(uint32_t*)(ol + (size_t)r1 * Ww + col) = pack_bf16(o2 - __bfloat162float(h2), o3 - __bfloat162float(h3));
    }
}

// ----------------------------------------------------------------------------
// Launcher
// ----------------------------------------------------------------------------
extern "C" void kernel_launch(void* const* d_in, const int* in_sizes, int n_in,
                              void* d_out, int out_size) {
    const float* x      = (const float*)d_in[0];
    const float* ln1_g  = (const float*)d_in[1];
    const float* ln1_b  = (const float*)d_in[2];
    const float* qkv_w  = (const float*)d_in[3];
    const float* qkv_b  = (const float*)d_in[4];
    const float* proj_w = (const float*)d_in[5];
    const float* proj_b = (const float*)d_in[6];
    const float* ln2_g  = (const float*)d_in[7];
    const float* ln2_b  = (const float*)d_in[8];
    const float* fc_w   = (const float*)d_in[9];
    const float* fc_b   = (const float*)d_in[10];
    const float* fc2_w  = (const float*)d_in[11];
    const float* fc2_b  = (const float*)d_in[12];
    float* out = (float*)d_out;

    float* x1;
    __nv_bfloat16 *ah, *al, *qh, *ql, *ath, *atl, *hh, *hl, *bh, *bl;
    cudaGetSymbolAddress((void**)&x1,  g_x1);
    cudaGetSymbolAddress((void**)&ah,  g_ah);
    cudaGetSymbolAddress((void**)&al,  g_al);
    cudaGetSymbolAddress((void**)&qh,  g_qh);
    cudaGetSymbolAddress((void**)&ql,  g_ql);
    cudaGetSymbolAddress((void**)&ath, g_ath);
    cudaGetSymbolAddress((void**)&atl, g_atl);
    cudaGetSymbolAddress((void**)&hh,  g_hh);
    cudaGetSymbolAddress((void**)&hl,  g_hl);
    cudaGetSymbolAddress((void**)&bh,  g_bh);
    cudaGetSymbolAddress((void**)&bl,  g_bl);

    cudaFuncSetAttribute(tc_gemm<2>, cudaFuncAttributeMaxDynamicSharedMemorySize, GS_TOTAL);
    cudaFuncSetAttribute(tc_gemm<3>, cudaFuncAttributeMaxDynamicSharedMemorySize, GS_TOTAL);
    cudaFuncSetAttribute(tc_gemm<4>, cudaFuncAttributeMaxDynamicSharedMemorySize, GS_TOTAL);
    cudaFuncSetAttribute(flash_tc, cudaFuncAttributeMaxDynamicSharedMemorySize, F_TOTAL);

    ln_kernel<<<ROWS, 256>>>(x, ln1_g, ln1_b, ah, al);
    splitT_kernel<<<dim3(3 * Ww / 32, Ww / 32), dim3(32, 8)>>>(qkv_w, bh, bl, Ww, 3 * Ww);
    tc_gemm<3><<<dim3(3 * Ww / 128, ROWS / 128), 256, GS_TOTAL>>>(
        ah, al, bh, bl, qkv_b, nullptr, nullptr, qh, ql, ROWS, 3 * Ww, Ww);
    flash_tc<<<dim3(Nn / 128, Hh, Bb), 256, F_TOTAL>>>(qh, ql, ath, atl);
    splitT_kernel<<<dim3(Ww / 32, Ww / 32), dim3(32, 8)>>>(proj_w, bh, bl, Ww, Ww);
    tc_gemm<2><<<dim3(Ww / 128, ROWS / 128), 256, GS_TOTAL>>>(
        ath, atl, bh, bl, proj_b, x, x1, nullptr, nullptr, ROWS, Ww, Ww);
    ln_kernel<<<ROWS, 256>>>(x1, ln2_g, ln2_b, ah, al);
    splitT_kernel<<<dim3(4 * Ww / 32, Ww / 32), dim3(32, 8)>>>(fc_w, bh, bl, Ww, 4 * Ww);
    tc_gemm<4><<<dim3(4 * Ww / 128, ROWS / 128), 256, GS_TOTAL>>>(
        ah, al, bh, bl, fc_b, nullptr, nullptr, hh, hl, ROWS, 4 * Ww, Ww);
    splitT_kernel<<<dim3(Ww / 32, 4 * Ww / 32), dim3(32, 8)>>>(fc2_w, bh, bl, 4 * Ww, Ww);
    tc_gemm<2><<<dim3(Ww / 128, ROWS / 128), 256, GS_TOTAL>>>(
        hh, hl, bh, bl, fc2_b, x1, out, nullptr, nullptr, ROWS, Ww, 4 * Ww);
}

// round 5
// speedup vs baseline: 4.3408x; 1.4465x over previous
#include <cuda_runtime.h>
#include <cuda_fp16.h>
#include <math.h>
#include <stdint.h>

// Problem constants
#define Bb 2
#define Nn 2048
#define Ww 1024
#define Hh 16
#define HDd 64
#define ROWS (Bb * Nn)   // 4096

// ----------------------------------------------------------------------------
// Scratch buffers (static __device__ globals; no runtime allocation allowed)
// ----------------------------------------------------------------------------
__device__ float g_x1[ROWS * Ww];            // post-attention residual (fp32)
__device__ __half g_ah[ROWS * Ww];           // ln output hi
__device__ __half g_al[ROWS * Ww];           // ln output lo
__device__ __half g_qh[ROWS * 3 * Ww];       // qkv hi (q pre-scaled)
__device__ __half g_ql[ROWS * 3 * Ww];       // qkv lo
__device__ __half g_ath[ROWS * Ww];          // attention out hi
__device__ __half g_atl[ROWS * Ww];          // attention out lo
__device__ __half g_hh[ROWS * 4 * Ww];       // gelu out hi
__device__ __half g_hl[ROWS * 4 * Ww];       // gelu out lo
__device__ __half g_bh[4 * Ww * Ww];         // weight fp16, [N,K] transposed

#define SWZ128(off) ((off) ^ (((off) >> 3) & 0x70))

__device__ __forceinline__ uint32_t smem_u32(const void* p) {
    uint32_t a;
    asm("{ .reg .u64 t; cvta.to.shared.u64 t, %1; cvt.u32.u64 %0, t; }" : "=r"(a) : "l"(p));
    return a;
}
__device__ __forceinline__ void cp16(uint32_t saddr, const void* g) {
    asm volatile("cp.async.cg.shared.global [%0], [%1], 16;" :: "r"(saddr), "l"(g));
}
#define CP_COMMIT() asm volatile("cp.async.commit_group;" ::: "memory")
#define CP_WAIT2()  asm volatile("cp.async.wait_group 2;" ::: "memory")
#define CP_WAIT1()  asm volatile("cp.async.wait_group 1;" ::: "memory")
#define CP_WAIT0()  asm volatile("cp.async.wait_group 0;" ::: "memory")

__device__ __forceinline__ void ldsm_x4(uint32_t& a0, uint32_t& a1, uint32_t& a2, uint32_t& a3,
                                        uint32_t addr) {
    asm volatile("ldmatrix.sync.aligned.m8n8.x4.shared.b16 {%0,%1,%2,%3}, [%4];"
                 : "=r"(a0), "=r"(a1), "=r"(a2), "=r"(a3) : "r"(addr));
}
__device__ __forceinline__ void ldsm_x2(uint32_t& b0, uint32_t& b1, uint32_t addr) {
    asm volatile("ldmatrix.sync.aligned.m8n8.x2.shared.b16 {%0,%1}, [%2];"
                 : "=r"(b0), "=r"(b1) : "r"(addr));
}
__device__ __forceinline__ void ldsm_x2t(uint32_t& b0, uint32_t& b1, uint32_t addr) {
    asm volatile("ldmatrix.sync.aligned.m8n8.x2.trans.shared.b16 {%0,%1}, [%2];"
                 : "=r"(b0), "=r"(b1) : "r"(addr));
}
__device__ __forceinline__ void mma_f16(float* c,
                                        uint32_t a0, uint32_t a1, uint32_t a2, uint32_t a3,
                                        uint32_t b0, uint32_t b1) {
    asm volatile(
        "mma.sync.aligned.m16n8k16.row.col.f32.f16.f16.f32 "
        "{%0,%1,%2,%3}, {%4,%5,%6,%7}, {%8,%9}, {%0,%1,%2,%3};"
        : "+f"(c[0]), "+f"(c[1]), "+f"(c[2]), "+f"(c[3])
        : "r"(a0), "r"(a1), "r"(a2), "r"(a3), "r"(b0), "r"(b1));
}
__device__ __forceinline__ uint32_t pack_h2(float a, float b) {
    __half2 t = __floats2half2_rn(a, b);
    return *(uint32_t*)&t;
}
__device__ __forceinline__ float gelu_exact(float v) {
    return 0.5f * v * (1.0f + erff(v * 0.70710678118654752f));
}

// ----------------------------------------------------------------------------
// transpose-convert: W fp32 [K,N] -> fp16 [N,K]
// ----------------------------------------------------------------------------
__global__ void convT_kernel(const float* __restrict__ w, __half* __restrict__ hi,
                             int K, int N) {
    __shared__ float t[32][33];
    int n0 = blockIdx.x * 32, k0 = blockIdx.y * 32;
    int tx = threadIdx.x, ty = threadIdx.y;   // 32 x 8
    #pragma unroll
    for (int i = 0; i < 32; i += 8)
        t[ty + i][tx] = w[(size_t)(k0 + ty + i) * N + n0 + tx];
    __syncthreads();
    #pragma unroll
    for (int i = 0; i < 32; i += 8)
        hi[(size_t)(n0 + ty + i) * K + k0 + tx] = __float2half(t[tx][ty + i]);
}

// ----------------------------------------------------------------------------
// cp.async 3-stage mma.sync fp16 GEMM. A split hi/lo (2 passes), B single fp16.
// C[M,N] = A[M,K] @ B^T (B stored [N,K]).
// CTA 128x128, K chunk 64, 8 warps (2x4), warp tile 64x32.
// EPI: 2 = bias+residual -> fp32; 3 = bias,q-scale -> fp16 hi/lo;
//      4 = bias+gelu -> fp16 hi/lo
// ----------------------------------------------------------------------------
#define GS_AH 0
#define GS_AL 16384
#define GS_B  32768
#define GS_STAGE 49152
#define GS_TOTAL (3 * GS_STAGE)

template <int EPI>
__global__ void __launch_bounds__(256)
tc_gemm(const __half* __restrict__ Ah, const __half* __restrict__ Al,
        const __half* __restrict__ B,
        const float* __restrict__ bias, const float* __restrict__ res,
        float* __restrict__ Cf, __half* __restrict__ Ch, __half* __restrict__ Cl,
        int M, int N, int K) {
    extern __shared__ char smem[];
    uint32_t sb = smem_u32(smem);
    const int tid = threadIdx.x, wid = tid >> 5, lid = tid & 31;
    const int bm = blockIdx.y * 128, bn = blockIdx.x * 128;
    const int wm = (wid & 1) * 64;
    const int wn = (wid >> 1) * 32;

    float acc[4][4][4];
    #pragma unroll
    for (int i = 0; i < 4; i++)
        #pragma unroll
        for (int j = 0; j < 4; j++)
            #pragma unroll
            for (int r = 0; r < 4; r++) acc[i][j][r] = 0.f;

    const int a_r  = lid & 15;
    const int a_kb = (lid >> 4) * 16;
    const int b_r  = lid & 7;
    const int b_kb = ((lid >> 3) & 1) * 16;

    const int nchunk = K >> 6;
    #define G_LOAD(ck, s) do { \
        const int _k0 = (ck) << 6; \
        uint32_t _dst = sb + (s) * GS_STAGE; \
        _Pragma("unroll") \
        for (int _i = 0; _i < 4; _i++) { \
            int _idx = _i * 256 + tid; \
            int _r = _idx >> 3, _c = (_idx & 7) * 16; \
            uint32_t _so = SWZ128(_r * 128 + _c); \
            cp16(_dst + GS_AH + _so, (const char*)(Ah + (size_t)(bm + _r) * K + _k0) + _c); \
            cp16(_dst + GS_AL + _so, (const char*)(Al + (size_t)(bm + _r) * K + _k0) + _c); \
            cp16(_dst + GS_B  + _so, (const char*)(B  + (size_t)(bn + _r) * K + _k0) + _c); \
        } \
        CP_COMMIT(); \
    } while (0)

    G_LOAD(0, 0);
    G_LOAD(1, 1);
    for (int ck = 0; ck < nchunk; ck++) {
        if (ck + 2 < nchunk) { G_LOAD(ck + 2, (ck + 2) % 3); CP_WAIT2(); }
        else if (ck + 1 < nchunk) CP_WAIT1();
        else CP_WAIT0();
        __syncthreads();
        uint32_t stg = sb + (ck % 3) * GS_STAGE;
        #pragma unroll
        for (int ks = 0; ks < 4; ks++) {
            uint32_t b[4][2];
            #pragma unroll
            for (int j = 0; j < 4; j++) {
                uint32_t off = SWZ128((wn + j * 8 + b_r) * 128 + ks * 32 + b_kb);
                ldsm_x2(b[j][0], b[j][1], stg + GS_B + off);
            }
            #pragma unroll
            for (int pass = 0; pass < 2; pass++) {
                const uint32_t sA = stg + (pass ? GS_AL : GS_AH);
                #pragma unroll
                for (int i = 0; i < 4; i++) {
                    uint32_t a0, a1, a2, a3;
                    uint32_t off = SWZ128((wm + i * 16 + a_r) * 128 + ks * 32 + a_kb);
                    ldsm_x4(a0, a1, a2, a3, sA + off);
                    #pragma unroll
                    for (int j = 0; j < 4; j++)
                        mma_f16(acc[i][j], a0, a1, a2, a3, b[j][0], b[j][1]);
                }
            }
        }
        __syncthreads();
    }
    #undef G_LOAD

    const int er = lid >> 2;
    const int ec = (lid & 3) * 2;
    #pragma unroll
    for (int i = 0; i < 4; i++) {
        #pragma unroll
        for (int j = 0; j < 4; j++) {
            int col = bn + wn + j * 8 + ec;
            float2 bi = *(const float2*)(bias + col);
            #pragma unroll
            for (int half = 0; half < 2; half++) {
                int row = bm + wm + i * 16 + er + half * 8;
                float ox = acc[i][j][half * 2 + 0] + bi.x;
                float oy = acc[i][j][half * 2 + 1] + bi.y;
                if (EPI == 2) {
                    float2 rv = *(const float2*)(res + (size_t)row * N + col);
                    float2 o = make_float2(ox + rv.x, oy + rv.y);
                    *(float2*)(Cf + (size_t)row * N + col) = o;
                } else {
                    if (EPI == 3) {
                        float s = ((col % 192) < 64) ? 0.125f : 1.0f;
                        ox *= s; oy *= s;
                    }
                    if (EPI == 4) { ox = gelu_exact(ox); oy = gelu_exact(oy); }
                    __half hx = __float2half(ox), hy = __float2half(oy);
                    *(uint32_t*)(Ch + (size_t)row * N + col) =
                        pack_h2(__half2float(hx), __half2float(hy));
                    *(uint32_t*)(Cl + (size_t)row * N + col) =
                        pack_h2(ox - __half2float(hx), oy - __half2float(hy));
                }
            }
        }
    }
}

// ----------------------------------------------------------------------------
// LayerNorm -> hi/lo fp16 outputs
// ----------------------------------------------------------------------------
__global__ void ln_kernel(const float* __restrict__ x, const float* __restrict__ g,
                          const float* __restrict__ beta,
                          __half* __restrict__ yh, __half* __restrict__ yl) {
    int row = blockIdx.x, tid = threadIdx.x;
    const float* xr = x + (size_t)row * Ww;
    float4 v = *(const float4*)(xr + tid * 4);
    float s = v.x + v.y + v.z + v.w;
    float ss = v.x * v.x + v.y * v.y + v.z * v.z + v.w * v.w;
    #pragma unroll
    for (int off = 16; off; off >>= 1) {
        s  += __shfl_xor_sync(0xffffffffu, s, off);
        ss += __shfl_xor_sync(0xffffffffu, ss, off);
    }
    __shared__ float sb[8], sq[8];
    if ((tid & 31) == 0) { sb[tid >> 5] = s; sq[tid >> 5] = ss; }
    __syncthreads();
    if (tid < 32) {
        float a  = (tid < 8) ? sb[tid] : 0.f;
        float b2 = (tid < 8) ? sq[tid] : 0.f;
        #pragma unroll
        for (int off = 4; off; off >>= 1) {
            a  += __shfl_xor_sync(0xffffffffu, a, off);
            b2 += __shfl_xor_sync(0xffffffffu, b2, off);
        }
        if (tid == 0) { sb[0] = a; sq[0] = b2; }
    }
    __syncthreads();
    float mean = sb[0] * (1.f / Ww);
    float var  = sq[0] * (1.f / Ww) - mean * mean;
    float rstd = rsqrtf(var + 1e-5f);
    float4 gv = *(const float4*)(g + tid * 4);
    float4 bv = *(const float4*)(beta + tid * 4);
    float o0 = (v.x - mean) * rstd * gv.x + bv.x;
    float o1 = (v.y - mean) * rstd * gv.y + bv.y;
    float o2 = (v.z - mean) * rstd * gv.z + bv.z;
    float o3 = (v.w - mean) * rstd * gv.w + bv.w;
    __half h0 = __float2half(o0), h1 = __float2half(o1);
    __half h2 = __float2half(o2), h3 = __float2half(o3);
    size_t base = (size_t)row * Ww + tid * 4;
    *(uint32_t*)(yh + base)     = pack_h2(__half2float(h0), __half2float(h1));
    *(uint32_t*)(yh + base + 2) = pack_h2(__half2float(h2), __half2float(h3));
    *(uint32_t*)(yl + base)     = pack_h2(o0 - __half2float(h0), o1 - __half2float(h1));
    *(uint32_t*)(yl + base + 2) = pack_h2(o2 - __half2float(h2), o3 - __half2float(h3));
}

// ----------------------------------------------------------------------------
// Tensor-core flash attention, fp16.
// Q split hi/lo (2-pass S); K, V single fp16; P split hi/lo (2-pass P@V).
// qh layout: [token][h*192 + {q|k|v}], q pre-scaled by 0.125.
// CTA: 128 queries x one head. 8 warps. 3-stage K/V pipeline.
// ----------------------------------------------------------------------------
#define F_QH 0
#define F_QL 16384
#define F_ST 32768
#define F_K  0
#define F_V  8192
#define F_STAGE 16384
#define F_TOTAL (F_ST + 3 * F_STAGE)

__global__ void __launch_bounds__(256)
flash_tc(const __half* __restrict__ qh, const __half* __restrict__ ql,
         __half* __restrict__ oh, __half* __restrict__ ol) {
    extern __shared__ char smem[];
    uint32_t sbm = smem_u32(smem);
    const int tid = threadIdx.x, wid = tid >> 5, lid = tid & 31;
    const int qt = blockIdx.x, h = blockIdx.y, b = blockIdx.z;
    const int wm = wid * 16;

    const size_t hcol = (size_t)h * 192;

    // Q hi/lo: 128 rows x 128B each (group 0)
    #pragma unroll
    for (int i = 0; i < 4; i++) {
        int idx = i * 256 + tid;
        int r = idx >> 3, c = (idx & 7) * 16;
        uint32_t so = SWZ128(r * 128 + c);
        const char* gq = (const char*)(qh + (size_t)(b * Nn + qt * 128 + r) * (3 * Ww) + hcol) + c;
        const char* gl = (const char*)(ql + (size_t)(b * Nn + qt * 128 + r) * (3 * Ww) + hcol) + c;
        cp16(sbm + F_QH + so, gq);
        cp16(sbm + F_QL + so, gl);
    }
    CP_COMMIT();

    #define F_LOAD(kt, s) do { \
        uint32_t _dst = sbm + F_ST + (s) * F_STAGE; \
        _Pragma("unroll") \
        for (int _i = 0; _i < 2; _i++) { \
            int _idx = _i * 256 + tid; \
            int _r = _idx >> 3, _c = (_idx & 7) * 16; \
            uint32_t _so = SWZ128(_r * 128 + _c); \
            size_t _row = (size_t)(b * Nn + (kt) * 64 + _r) * (3 * Ww) + hcol; \
            cp16(_dst + F_K + _so, (const char*)(qh + _row + 64) + _c); \
            cp16(_dst + F_V + _so, (const char*)(qh + _row + 128) + _c); \
        } \
        CP_COMMIT(); \
    } while (0)

    F_LOAD(0, 0);
    F_LOAD(1, 1);

    const int a_r  = lid & 15;
    const int a_kb = (lid >> 4) * 16;
    const int b_r  = lid & 7;
    const int b_kb = ((lid >> 3) & 1) * 16;

    float O[8][4];
    #pragma unroll
    for (int j = 0; j < 8; j++)
        #pragma unroll
        for (int r = 0; r < 4; r++) O[j][r] = 0.f;
    float m0 = -INFINITY, m1 = -INFINITY, l0 = 0.f, l1 = 0.f;

    const int NKT = Nn / 64;
    for (int kt = 0; kt < NKT; kt++) {
        if (kt + 2 < NKT) { F_LOAD(kt + 2, (kt + 2) % 3); CP_WAIT2(); }
        else if (kt + 1 < NKT) CP_WAIT1();
        else CP_WAIT0();
        __syncthreads();
        uint32_t stg = sbm + F_ST + (kt % 3) * F_STAGE;

        // ---- S = Q K^T (2 passes: Qh, Ql) ----
        float S[8][4];
        #pragma unroll
        for (int j = 0; j < 8; j++)
            #pragma unroll
            for (int r = 0; r < 4; r++) S[j][r] = 0.f;
        #pragma unroll
        for (int ks = 0; ks < 4; ks++) {
            uint32_t bk[8][2];
            #pragma unroll
            for (int j = 0; j < 8; j++)
                ldsm_x2(bk[j][0], bk[j][1], stg + F_K + SWZ128((j * 8 + b_r) * 128 + ks * 32 + b_kb));
            #pragma unroll
            for (int pass = 0; pass < 2; pass++) {
                const uint32_t sA = sbm + (pass ? F_QL : F_QH);
                uint32_t a0, a1, a2, a3;
                ldsm_x4(a0, a1, a2, a3, sA + SWZ128((wm + a_r) * 128 + ks * 32 + a_kb));
                #pragma unroll
                for (int j = 0; j < 8; j++)
                    mma_f16(S[j], a0, a1, a2, a3, bk[j][0], bk[j][1]);
            }
        }

        // ---- online softmax ----
        float mx0 = -INFINITY, mx1 = -INFINITY;
        #pragma unroll
        for (int j = 0; j < 8; j++) {
            mx0 = fmaxf(mx0, fmaxf(S[j][0], S[j][1]));
            mx1 = fmaxf(mx1, fmaxf(S[j][2], S[j][3]));
        }
        mx0 = fmaxf(mx0, __shfl_xor_sync(0xffffffffu, mx0, 1));
        mx0 = fmaxf(mx0, __shfl_xor_sync(0xffffffffu, mx0, 2));
        mx1 = fmaxf(mx1, __shfl_xor_sync(0xffffffffu, mx1, 1));
        mx1 = fmaxf(mx1, __shfl_xor_sync(0xffffffffu, mx1, 2));
        float nm0 = fmaxf(m0, mx0), nm1 = fmaxf(m1, mx1);
        float al0 = __expf(m0 - nm0), al1 = __expf(m1 - nm1);
        float s0 = 0.f, s1 = 0.f;
        #pragma unroll
        for (int j = 0; j < 8; j++) {
            S[j][0] = __expf(S[j][0] - nm0); s0 += S[j][0];
            S[j][1] = __expf(S[j][1] - nm0); s0 += S[j][1];
            S[j][2] = __expf(S[j][2] - nm1); s1 += S[j][2];
            S[j][3] = __expf(S[j][3] - nm1); s1 += S[j][3];
        }
        s0 += __shfl_xor_sync(0xffffffffu, s0, 1);
        s0 += __shfl_xor_sync(0xffffffffu, s0, 2);
        s1 += __shfl_xor_sync(0xffffffffu, s1, 1);
        s1 += __shfl_xor_sync(0xffffffffu, s1, 2);
        l0 = l0 * al0 + s0;
        l1 = l1 * al1 + s1;
        m0 = nm0; m1 = nm1;
        #pragma unroll
        for (int j = 0; j < 8; j++) {
            O[j][0] *= al0; O[j][1] *= al0;
            O[j][2] *= al1; O[j][3] *= al1;
        }

        // ---- O += P V (2 passes: Ph, Pl; V single) ----
        #pragma unroll
        for (int t = 0; t < 4; t++) {
            uint32_t ph[4], pl[4];
            #pragma unroll
            for (int half = 0; half < 2; half++) {
                int j = 2 * t + half;
                float p0 = S[j][0], p1 = S[j][1], p2 = S[j][2], p3 = S[j][3];
                __half h0 = __float2half(p0), h1 = __float2half(p1);
                __half h2 = __float2half(p2), h3 = __float2half(p3);
                ph[half * 2 + 0] = pack_h2(__half2float(h0), __half2float(h1));
                ph[half * 2 + 1] = pack_h2(__half2float(h2), __half2float(h3));
                pl[half * 2 + 0] = pack_h2(p0 - __half2float(h0), p1 - __half2float(h1));
                pl[half * 2 + 1] = pack_h2(p2 - __half2float(h2), p3 - __half2float(h3));
            }
            uint32_t vrow = t * 16 + (lid & 15);
            #pragma unroll
            for (int j = 0; j < 8; j++) {
                uint32_t off = SWZ128(vrow * 128 + j * 16);
                uint32_t v0, v1;
                ldsm_x2t(v0, v1, stg + F_V + off);
                mma_f16(O[j], ph[0], ph[1], ph[2], ph[3], v0, v1);
                mma_f16(O[j], pl[0], pl[1], pl[2], pl[3], v0, v1);
            }
        }
        __syncthreads();
    }
    #undef F_LOAD

    float inv0 = 1.f / l0, inv1 = 1.f / l1;
    int r0 = b * Nn + qt * 128 + wm + (lid >> 2);
    int r1 = r0 + 8;
    int cb = h * 64 + (lid & 3) * 2;
    #pragma unroll
    for (int j = 0; j < 8; j++) {
        int col = cb + j * 8;
        float o0 = O[j][0] * inv0, o1 = O[j][1] * inv0;
        float o2 = O[j][2] * inv1, o3 = O[j][3] * inv1;
        __half h0 = __float2half(o0), h1 = __float2half(o1);
        __half h2 = __float2half(o2), h3 = __float2half(o3);
        *(uint32_t*)(oh + (size_t)r0 * Ww + col) = pack_h2(__half2float(h0), __half2float(h1));
        *(uint32_t*)(oh + (size_t)r1 * Ww + col) = pack_h2(__half2float(h2), __half2float(h3));
        *(uint32_t*)(ol + (size_t)r0 * Ww + col) = pack_h2(o0 - __half2float(h0), o1 - __half2float(h1));
        *(uint32_t*)(ol + (size_t)r1 * Ww + col) = pack_h2(o2 - __half2float(h2), o3 - __half2float(h3));
    }
}

// ----------------------------------------------------------------------------
// Launcher
// ----------------------------------------------------------------------------
extern "C" void kernel_launch(void* const* d_in, const int* in_sizes, int n_in,
                              void* d_out, int out_size) {
    const float* x      = (const float*)d_in[0];
    const float* ln1_g  = (const float*)d_in[1];
    const float* ln1_b  = (const float*)d_in[2];
    const float* qkv_w  = (const float*)d_in[3];
    const float* qkv_b  = (const float*)d_in[4];
    const float* proj_w = (const float*)d_in[5];
    const float* proj_b = (const float*)d_in[6];
    const float* ln2_g  = (const float*)d_in[7];
    const float* ln2_b  = (const float*)d_in[8];
    const float* fc_w   = (const float*)d_in[9];
    const float* fc_b   = (const float*)d_in[10];
    const float* fc2_w  = (const float*)d_in[11];
    const float* fc2_b  = (const float*)d_in[12];
    float* out = (float*)d_out;

    float* x1;
    __half *ah, *al, *qh, *ql, *ath, *atl, *hh, *hl, *bh;
    cudaGetSymbolAddress((void**)&x1,  g_x1);
    cudaGetSymbolAddress((void**)&ah,  g_ah);
    cudaGetSymbolAddress((void**)&al,  g_al);
    cudaGetSymbolAddress((void**)&qh,  g_qh);
    cudaGetSymbolAddress((void**)&ql,  g_ql);
    cudaGetSymbolAddress((void**)&ath, g_ath);
    cudaGetSymbolAddress((void**)&atl, g_atl);
    cudaGetSymbolAddress((void**)&hh,  g_hh);
    cudaGetSymbolAddress((void**)&hl,  g_hl);
    cudaGetSymbolAddress((void**)&bh,  g_bh);

    cudaFuncSetAttribute(tc_gemm<2>, cudaFuncAttributeMaxDynamicSharedMemorySize, GS_TOTAL);
    cudaFuncSetAttribute(tc_gemm<3>, cudaFuncAttributeMaxDynamicSharedMemorySize, GS_TOTAL);
    cudaFuncSetAttribute(tc_gemm<4>, cudaFuncAttributeMaxDynamicSharedMemorySize, GS_TOTAL);
    cudaFuncSetAttribute(flash_tc, cudaFuncAttributeMaxDynamicSharedMemorySize, F_TOTAL);

    ln_kernel<<<ROWS, 256>>>(x, ln1_g, ln1_b, ah, al);
    convT_kernel<<<dim3(3 * Ww / 32, Ww / 32), dim3(32, 8)>>>(qkv_w, bh, Ww, 3 * Ww);
    tc_gemm<3><<<dim3(3 * Ww / 128, ROWS / 128), 256, GS_TOTAL>>>(
        ah, al, bh, qkv_b, nullptr, nullptr, qh, ql, ROWS, 3 * Ww, Ww);
    flash_tc<<<dim3(Nn / 128, Hh, Bb), 256, F_TOTAL>>>(qh, ql, ath, atl);
    convT_kernel<<<dim3(Ww / 32, Ww / 32), dim3(32, 8)>>>(proj_w, bh, Ww, Ww);
    tc_gemm<2><<<dim3(Ww / 128, ROWS / 128), 256, GS_TOTAL>>>(
        ath, atl, bh, proj_b, x, x1, nullptr, nullptr, ROWS, Ww, Ww);
    ln_kernel<<<ROWS, 256>>>(x1, ln2_g, ln2_b, ah, al);
    convT_kernel<<<dim3(4 * Ww / 32, Ww / 32), dim3(32, 8)>>>(fc_w, bh, Ww, 4 * Ww);
    tc_gemm<4><<<dim3(4 * Ww / 128, ROWS / 128), 256, GS_TOTAL>>>(
        ah, al, bh, fc_b, nullptr, nullptr, hh, hl, ROWS, 4 * Ww, Ww);
    convT_kernel<<<dim3(Ww / 32, 4 * Ww / 32), dim3(32, 8)>>>(fc2_w, bh, 4 * Ww, Ww);
    tc_gemm<2><<<dim3(Ww / 128, ROWS / 128), 256, GS_TOTAL>>>(
        hh, hl, bh, fc2_b, x1, out, nullptr, nullptr, ROWS, Ww, 4 * Ww);
}

// round 6
// speedup vs baseline: 4.3558x; 1.0035x over previous
#include <cuda_runtime.h>
#include <cuda_fp16.h>
#include <math.h>
#include <stdint.h>

// Problem constants
#define Bb 2
#define Nn 2048
#define Ww 1024
#define Hh 16
#define HDd 64
#define ROWS (Bb * Nn)   // 4096

// ----------------------------------------------------------------------------
// Scratch buffers
// ----------------------------------------------------------------------------
__device__ float g_x1[ROWS * Ww];            // post-attention residual (fp32)
__device__ __half g_ah[ROWS * Ww];           // ln output hi
__device__ __half g_al[ROWS * Ww];           // ln output lo
__device__ __half g_qh[ROWS * 3 * Ww];       // qkv hi (q pre-scaled)
__device__ __half g_ql[ROWS * 3 * Ww];       // qkv lo
__device__ __half g_ath[ROWS * Ww];          // attention out hi
__device__ __half g_atl[ROWS * Ww];          // attention out lo
__device__ __half g_hh[ROWS * 4 * Ww];       // gelu out hi
__device__ __half g_hl[ROWS * 4 * Ww];       // gelu out lo
__device__ __half g_bh[4 * Ww * Ww];         // weight fp16, [N,K] transposed

#define SWZ128(off) ((off) ^ (((off) >> 3) & 0x70))

__device__ __forceinline__ uint32_t smem_u32(const void* p) {
    uint32_t a;
    asm("{ .reg .u64 t; cvta.to.shared.u64 t, %1; cvt.u32.u64 %0, t; }" : "=r"(a) : "l"(p));
    return a;
}
__device__ __forceinline__ void cp16(uint32_t saddr, const void* g) {
    asm volatile("cp.async.cg.shared.global [%0], [%1], 16;" :: "r"(saddr), "l"(g));
}
#define CP_COMMIT() asm volatile("cp.async.commit_group;" ::: "memory")
#define CP_WAIT2()  asm volatile("cp.async.wait_group 2;" ::: "memory")
#define CP_WAIT1()  asm volatile("cp.async.wait_group 1;" ::: "memory")
#define CP_WAIT0()  asm volatile("cp.async.wait_group 0;" ::: "memory")

__device__ __forceinline__ void ldsm_x4(uint32_t& a0, uint32_t& a1, uint32_t& a2, uint32_t& a3,
                                        uint32_t addr) {
    asm volatile("ldmatrix.sync.aligned.m8n8.x4.shared.b16 {%0,%1,%2,%3}, [%4];"
                 : "=r"(a0), "=r"(a1), "=r"(a2), "=r"(a3) : "r"(addr));
}
__device__ __forceinline__ void ldsm_x2(uint32_t& b0, uint32_t& b1, uint32_t addr) {
    asm volatile("ldmatrix.sync.aligned.m8n8.x2.shared.b16 {%0,%1}, [%2];"
                 : "=r"(b0), "=r"(b1) : "r"(addr));
}
__device__ __forceinline__ void ldsm_x2t(uint32_t& b0, uint32_t& b1, uint32_t addr) {
    asm volatile("ldmatrix.sync.aligned.m8n8.x2.trans.shared.b16 {%0,%1}, [%2];"
                 : "=r"(b0), "=r"(b1) : "r"(addr));
}
__device__ __forceinline__ void mma_f16(float* c,
                                        uint32_t a0, uint32_t a1, uint32_t a2, uint32_t a3,
                                        uint32_t b0, uint32_t b1) {
    asm volatile(
        "mma.sync.aligned.m16n8k16.row.col.f32.f16.f16.f32 "
        "{%0,%1,%2,%3}, {%4,%5,%6,%7}, {%8,%9}, {%0,%1,%2,%3};"
        : "+f"(c[0]), "+f"(c[1]), "+f"(c[2]), "+f"(c[3])
        : "r"(a0), "r"(a1), "r"(a2), "r"(a3), "r"(b0), "r"(b1));
}
__device__ __forceinline__ uint32_t pack_h2(float a, float b) {
    __half2 t = __floats2half2_rn(a, b);
    return *(uint32_t*)&t;
}
__device__ __forceinline__ float gelu_exact(float v) {
    return 0.5f * v * (1.0f + erff(v * 0.70710678118654752f));
}

// ----------------------------------------------------------------------------
// transpose-convert: W fp32 [K,N] -> fp16 [N,K]
// ----------------------------------------------------------------------------
__global__ void convT_kernel(const float* __restrict__ w, __half* __restrict__ hi,
                             int K, int N) {
    __shared__ float t[32][33];
    int n0 = blockIdx.x * 32, k0 = blockIdx.y * 32;
    int tx = threadIdx.x, ty = threadIdx.y;   // 32 x 8
    #pragma unroll
    for (int i = 0; i < 32; i += 8)
        t[ty + i][tx] = w[(size_t)(k0 + ty + i) * N + n0 + tx];
    __syncthreads();
    #pragma unroll
    for (int i = 0; i < 32; i += 8)
        hi[(size_t)(n0 + ty + i) * K + k0 + tx] = __float2half(t[tx][ty + i]);
}

// ----------------------------------------------------------------------------
// cp.async 3-stage mma.sync fp16 GEMM. A split hi/lo (2 passes), B single fp16.
// C[M,N] = A[M,K] @ B^T (B stored [N,K]).
// CTA 128x256, K chunk 64, 8 warps (2x4), warp tile 64x64.
// EPI: 2 = bias+residual -> fp32; 3 = bias,q-scale -> fp16 hi/lo;
//      4 = bias+gelu -> fp16 hi/lo
// ----------------------------------------------------------------------------
#define GS_AH 0
#define GS_AL 16384
#define GS_B  32768
#define GS_STAGE 65536
#define GS_TOTAL (3 * GS_STAGE)   // 192 KB

template <int EPI>
__global__ void __launch_bounds__(256)
tc_gemm(const __half* __restrict__ Ah, const __half* __restrict__ Al,
        const __half* __restrict__ B,
        const float* __restrict__ bias, const float* __restrict__ res,
        float* __restrict__ Cf, __half* __restrict__ Ch, __half* __restrict__ Cl,
        int M, int N, int K) {
    extern __shared__ char smem[];
    uint32_t sb = smem_u32(smem);
    const int tid = threadIdx.x, wid = tid >> 5, lid = tid & 31;
    const int bm = blockIdx.y * 128, bn = blockIdx.x * 256;
    const int wm = (wid & 1) * 64;
    const int wn = (wid >> 1) * 64;

    float acc[4][8][4];
    #pragma unroll
    for (int i = 0; i < 4; i++)
        #pragma unroll
        for (int j = 0; j < 8; j++)
            #pragma unroll
            for (int r = 0; r < 4; r++) acc[i][j][r] = 0.f;

    const int a_r  = lid & 15;
    const int a_kb = (lid >> 4) * 16;
    const int b_r  = lid & 7;
    const int b_kb = ((lid >> 3) & 1) * 16;

    const int nchunk = K >> 6;
    #define G_LOAD(ck, s) do { \
        const int _k0 = (ck) << 6; \
        uint32_t _dst = sb + (s) * GS_STAGE; \
        _Pragma("unroll") \
        for (int _i = 0; _i < 4; _i++) { \
            int _idx = _i * 256 + tid; \
            int _r = _idx >> 3, _c = (_idx & 7) * 16; \
            uint32_t _so = SWZ128(_r * 128 + _c); \
            cp16(_dst + GS_AH + _so, (const char*)(Ah + (size_t)(bm + _r) * K + _k0) + _c); \
            cp16(_dst + GS_AL + _so, (const char*)(Al + (size_t)(bm + _r) * K + _k0) + _c); \
        } \
        _Pragma("unroll") \
        for (int _i = 0; _i < 8; _i++) { \
            int _idx = _i * 256 + tid; \
            int _r = _idx >> 3, _c = (_idx & 7) * 16; \
            uint32_t _so = SWZ128(_r * 128 + _c); \
            cp16(_dst + GS_B + _so, (const char*)(B + (size_t)(bn + _r) * K + _k0) + _c); \
        } \
        CP_COMMIT(); \
    } while (0)

    G_LOAD(0, 0);
    G_LOAD(1, 1);
    for (int ck = 0; ck < nchunk; ck++) {
        if (ck + 2 < nchunk) { G_LOAD(ck + 2, (ck + 2) % 3); CP_WAIT2(); }
        else if (ck + 1 < nchunk) CP_WAIT1();
        else CP_WAIT0();
        __syncthreads();
        uint32_t stg = sb + (ck % 3) * GS_STAGE;
        #pragma unroll
        for (int pass = 0; pass < 2; pass++) {
            const uint32_t sA = stg + (pass ? GS_AL : GS_AH);
            #pragma unroll
            for (int ks = 0; ks < 4; ks++) {
                uint32_t a[4][4];
                #pragma unroll
                for (int i = 0; i < 4; i++) {
                    uint32_t off = SWZ128((wm + i * 16 + a_r) * 128 + ks * 32 + a_kb);
                    ldsm_x4(a[i][0], a[i][1], a[i][2], a[i][3], sA + off);
                }
                #pragma unroll
                for (int j = 0; j < 8; j++) {
                    uint32_t b0, b1;
                    uint32_t off = SWZ128((wn + j * 8 + b_r) * 128 + ks * 32 + b_kb);
                    ldsm_x2(b0, b1, stg + GS_B + off);
                    #pragma unroll
                    for (int i = 0; i < 4; i++)
                        mma_f16(acc[i][j], a[i][0], a[i][1], a[i][2], a[i][3], b0, b1);
                }
            }
        }
        __syncthreads();
    }
    #undef G_LOAD

    const int er = lid >> 2;
    const int ec = (lid & 3) * 2;
    #pragma unroll
    for (int i = 0; i < 4; i++) {
        #pragma unroll
        for (int j = 0; j < 8; j++) {
            int col = bn + wn + j * 8 + ec;
            float2 bi = *(const float2*)(bias + col);
            #pragma unroll
            for (int half = 0; half < 2; half++) {
                int row = bm + wm + i * 16 + er + half * 8;
                float ox = acc[i][j][half * 2 + 0] + bi.x;
                float oy = acc[i][j][half * 2 + 1] + bi.y;
                if (EPI == 2) {
                    float2 rv = *(const float2*)(res + (size_t)row * N + col);
                    float2 o = make_float2(ox + rv.x, oy + rv.y);
                    *(float2*)(Cf + (size_t)row * N + col) = o;
                } else {
                    if (EPI == 3) {
                        float s = ((col % 192) < 64) ? 0.125f : 1.0f;
                        ox *= s; oy *= s;
                    }
                    if (EPI == 4) { ox = gelu_exact(ox); oy = gelu_exact(oy); }
                    __half hx = __float2half(ox), hy = __float2half(oy);
                    *(uint32_t*)(Ch + (size_t)row * N + col) =
                        pack_h2(__half2float(hx), __half2float(hy));
                    *(uint32_t*)(Cl + (size_t)row * N + col) =
                        pack_h2(ox - __half2float(hx), oy - __half2float(hy));
                }
            }
        }
    }
}

// ----------------------------------------------------------------------------
// LayerNorm -> hi/lo fp16 outputs
// ----------------------------------------------------------------------------
__global__ void ln_kernel(const float* __restrict__ x, const float* __restrict__ g,
                          const float* __restrict__ beta,
                          __half* __restrict__ yh, __half* __restrict__ yl) {
    int row = blockIdx.x, tid = threadIdx.x;
    const float* xr = x + (size_t)row * Ww;
    float4 v = *(const float4*)(xr + tid * 4);
    float s = v.x + v.y + v.z + v.w;
    float ss = v.x * v.x + v.y * v.y + v.z * v.z + v.w * v.w;
    #pragma unroll
    for (int off = 16; off; off >>= 1) {
        s  += __shfl_xor_sync(0xffffffffu, s, off);
        ss += __shfl_xor_sync(0xffffffffu, ss, off);
    }
    __shared__ float sb[8], sq[8];
    if ((tid & 31) == 0) { sb[tid >> 5] = s; sq[tid >> 5] = ss; }
    __syncthreads();
    if (tid < 32) {
        float a  = (tid < 8) ? sb[tid] : 0.f;
        float b2 = (tid < 8) ? sq[tid] : 0.f;
        #pragma unroll
        for (int off = 4; off; off >>= 1) {
            a  += __shfl_xor_sync(0xffffffffu, a, off);
            b2 += __shfl_xor_sync(0xffffffffu, b2, off);
        }
        if (tid == 0) { sb[0] = a; sq[0] = b2; }
    }
    __syncthreads();
    float mean = sb[0] * (1.f / Ww);
    float var  = sq[0] * (1.f / Ww) - mean * mean;
    float rstd = rsqrtf(var + 1e-5f);
    float4 gv = *(const float4*)(g + tid * 4);
    float4 bv = *(const float4*)(beta + tid * 4);
    float o0 = (v.x - mean) * rstd * gv.x + bv.x;
    float o1 = (v.y - mean) * rstd * gv.y + bv.y;
    float o2 = (v.z - mean) * rstd * gv.z + bv.z;
    float o3 = (v.w - mean) * rstd * gv.w + bv.w;
    __half h0 = __float2half(o0), h1 = __float2half(o1);
    __half h2 = __float2half(o2), h3 = __float2half(o3);
    size_t base = (size_t)row * Ww + tid * 4;
    *(uint32_t*)(yh + base)     = pack_h2(__half2float(h0), __half2float(h1));
    *(uint32_t*)(yh + base + 2) = pack_h2(__half2float(h2), __half2float(h3));
    *(uint32_t*)(yl + base)     = pack_h2(o0 - __half2float(h0), o1 - __half2float(h1));
    *(uint32_t*)(yl + base + 2) = pack_h2(o2 - __half2float(h2), o3 - __half2float(h3));
}

// ----------------------------------------------------------------------------
// Tensor-core flash attention, fp16.
// Q split hi/lo (2-pass S); K, V, P single fp16 (1-pass P@V).
// ----------------------------------------------------------------------------
#define F_QH 0
#define F_QL 16384
#define F_ST 32768
#define F_K  0
#define F_V  8192
#define F_STAGE 16384
#define F_TOTAL (F_ST + 3 * F_STAGE)

__global__ void __launch_bounds__(256)
flash_tc(const __half* __restrict__ qh, const __half* __restrict__ ql,
         __half* __restrict__ oh, __half* __restrict__ ol) {
    extern __shared__ char smem[];
    uint32_t sbm = smem_u32(smem);
    const int tid = threadIdx.x, wid = tid >> 5, lid = tid & 31;
    const int qt = blockIdx.x, h = blockIdx.y, b = blockIdx.z;
    const int wm = wid * 16;

    const size_t hcol = (size_t)h * 192;

    #pragma unroll
    for (int i = 0; i < 4; i++) {
        int idx = i * 256 + tid;
        int r = idx >> 3, c = (idx & 7) * 16;
        uint32_t so = SWZ128(r * 128 + c);
        const char* gq = (const char*)(qh + (size_t)(b * Nn + qt * 128 + r) * (3 * Ww) + hcol) + c;
        const char* gl = (const char*)(ql + (size_t)(b * Nn + qt * 128 + r) * (3 * Ww) + hcol) + c;
        cp16(sbm + F_QH + so, gq);
        cp16(sbm + F_QL + so, gl);
    }
    CP_COMMIT();

    #define F_LOAD(kt, s) do { \
        uint32_t _dst = sbm + F_ST + (s) * F_STAGE; \
        _Pragma("unroll") \
        for (int _i = 0; _i < 2; _i++) { \
            int _idx = _i * 256 + tid; \
            int _r = _idx >> 3, _c = (_idx & 7) * 16; \
            uint32_t _so = SWZ128(_r * 128 + _c); \
            size_t _row = (size_t)(b * Nn + (kt) * 64 + _r) * (3 * Ww) + hcol; \
            cp16(_dst + F_K + _so, (const char*)(qh + _row + 64) + _c); \
            cp16(_dst + F_V + _so, (const char*)(qh + _row + 128) + _c); \
        } \
        CP_COMMIT(); \
    } while (0)

    F_LOAD(0, 0);
    F_LOAD(1, 1);

    const int a_r  = lid & 15;
    const int a_kb = (lid >> 4) * 16;
    const int b_r  = lid & 7;
    const int b_kb = ((lid >> 3) & 1) * 16;

    float O[8][4];
    #pragma unroll
    for (int j = 0; j < 8; j++)
        #pragma unroll
        for (int r = 0; r < 4; r++) O[j][r] = 0.f;
    float m0 = -INFINITY, m1 = -INFINITY, l0 = 0.f, l1 = 0.f;

    const int NKT = Nn / 64;
    for (int kt = 0; kt < NKT; kt++) {
        if (kt + 2 < NKT) { F_LOAD(kt + 2, (kt + 2) % 3); CP_WAIT2(); }
        else if (kt + 1 < NKT) CP_WAIT1();
        else CP_WAIT0();
        __syncthreads();
        uint32_t stg = sbm + F_ST + (kt % 3) * F_STAGE;

        float S[8][4];
        #pragma unroll
        for (int j = 0; j < 8; j++)
            #pragma unroll
            for (int r = 0; r < 4; r++) S[j][r] = 0.f;
        #pragma unroll
        for (int ks = 0; ks < 4; ks++) {
            uint32_t bk[8][2];
            #pragma unroll
            for (int j = 0; j < 8; j++)
                ldsm_x2(bk[j][0], bk[j][1], stg + F_K + SWZ128((j * 8 + b_r) * 128 + ks * 32 + b_kb));
            #pragma unroll
            for (int pass = 0; pass < 2; pass++) {
                const uint32_t sA = sbm + (pass ? F_QL : F_QH);
                uint32_t a0, a1, a2, a3;
                ldsm_x4(a0, a1, a2, a3, sA + SWZ128((wm + a_r) * 128 + ks * 32 + a_kb));
                #pragma unroll
                for (int j = 0; j < 8; j++)
                    mma_f16(S[j], a0, a1, a2, a3, bk[j][0], bk[j][1]);
            }
        }

        float mx0 = -INFINITY, mx1 = -INFINITY;
        #pragma unroll
        for (int j = 0; j < 8; j++) {
            mx0 = fmaxf(mx0, fmaxf(S[j][0], S[j][1]));
            mx1 = fmaxf(mx1, fmaxf(S[j][2], S[j][3]));
        }
        mx0 = fmaxf(mx0, __shfl_xor_sync(0xffffffffu, mx0, 1));
        mx0 = fmaxf(mx0, __shfl_xor_sync(0xffffffffu, mx0, 2));
        mx1 = fmaxf(mx1, __shfl_xor_sync(0xffffffffu, mx1, 1));
        mx1 = fmaxf(mx1, __shfl_xor_sync(0xffffffffu, mx1, 2));
        float nm0 = fmaxf(m0, mx0), nm1 = fmaxf(m1, mx1);
        float al0 = __expf(m0 - nm0), al1 = __expf(m1 - nm1);
        float s0 = 0.f, s1 = 0.f;
        #pragma unroll
        for (int j = 0; j < 8; j++) {
            S[j][0] = __expf(S[j][0] - nm0); s0 += S[j][0];
            S[j][1] = __expf(S[j][1] - nm0); s0 += S[j][1];
            S[j][2] = __expf(S[j][2] - nm1); s1 += S[j][2];
            S[j][3] = __expf(S[j][3] - nm1); s1 += S[j][3];
        }
        s0 += __shfl_xor_sync(0xffffffffu, s0, 1);
        s0 += __shfl_xor_sync(0xffffffffu, s0, 2);
        s1 += __shfl_xor_sync(0xffffffffu, s1, 1);
        s1 += __shfl_xor_sync(0xffffffffu, s1, 2);
        l0 = l0 * al0 + s0;
        l1 = l1 * al1 + s1;
        m0 = nm0; m1 = nm1;
        #pragma unroll
        for (int j = 0; j < 8; j++) {
            O[j][0] *= al0; O[j][1] *= al0;
            O[j][2] *= al1; O[j][3] *= al1;
        }

        // O += P V, single-pass fp16 P
        #pragma unroll
        for (int t = 0; t < 4; t++) {
            uint32_t ph[4];
            #pragma unroll
            for (int half = 0; half < 2; half++) {
                int j = 2 * t + half;
                ph[half * 2 + 0] = pack_h2(S[j][0], S[j][1]);
                ph[half * 2 + 1] = pack_h2(S[j][2], S[j][3]);
            }
            uint32_t vrow = t * 16 + (lid & 15);
            #pragma unroll
            for (int j = 0; j < 8; j++) {
                uint32_t off = SWZ128(vrow * 128 + j * 16);
                uint32_t v0, v1;
                ldsm_x2t(v0, v1, stg + F_V + off);
                mma_f16(O[j], ph[0], ph[1], ph[2], ph[3], v0, v1);
            }
        }
        __syncthreads();
    }
    #undef F_LOAD

    float inv0 = 1.f / l0, inv1 = 1.f / l1;
    int r0 = b * Nn + qt * 128 + wm + (lid >> 2);
    int r1 = r0 + 8;
    int cb = h * 64 + (lid & 3) * 2;
    #pragma unroll
    for (int j = 0; j < 8; j++) {
        int col = cb + j * 8;
        float o0 = O[j][0] * inv0, o1 = O[j][1] * inv0;
        float o2 = O[j][2] * inv1, o3 = O[j][3] * inv1;
        __half h0 = __float2half(o0), h1 = __float2half(o1);
        __half h2 = __float2half(o2), h3 = __float2half(o3);
        *(uint32_t*)(oh + (size_t)r0 * Ww + col) = pack_h2(__half2float(h0), __half2float(h1));
        *(uint32_t*)(oh + (size_t)r1 * Ww + col) = pack_h2(__half2float(h2), __half2float(h3));
        *(uint32_t*)(ol + (size_t)r0 * Ww + col) = pack_h2(o0 - __half2float(h0), o1 - __half2float(h1));
        *(uint32_t*)(ol + (size_t)r1 * Ww + col) = pack_h2(o2 - __half2float(h2), o3 - __half2float(h3));
    }
}

// ----------------------------------------------------------------------------
// Launcher
// ----------------------------------------------------------------------------
extern "C" void kernel_launch(void* const* d_in, const int* in_sizes, int n_in,
                              void* d_out, int out_size) {
    const float* x      = (const float*)d_in[0];
    const float* ln1_g  = (const float*)d_in[1];
    const float* ln1_b  = (const float*)d_in[2];
    const float* qkv_w  = (const float*)d_in[3];
    const float* qkv_b  = (const float*)d_in[4];
    const float* proj_w = (const float*)d_in[5];
    const float* proj_b = (const float*)d_in[6];
    const float* ln2_g  = (const float*)d_in[7];
    const float* ln2_b  = (const float*)d_in[8];
    const float* fc_w   = (const float*)d_in[9];
    const float* fc_b   = (const float*)d_in[10];
    const float* fc2_w  = (const float*)d_in[11];
    const float* fc2_b  = (const float*)d_in[12];
    float* out = (float*)d_out;

    float* x1;
    __half *ah, *al, *qh, *ql, *ath, *atl, *hh, *hl, *bh;
    cudaGetSymbolAddress((void**)&x1,  g_x1);
    cudaGetSymbolAddress((void**)&ah,  g_ah);
    cudaGetSymbolAddress((void**)&al,  g_al);
    cudaGetSymbolAddress((void**)&qh,  g_qh);
    cudaGetSymbolAddress((void**)&ql,  g_ql);
    cudaGetSymbolAddress((void**)&ath, g_ath);
    cudaGetSymbolAddress((void**)&atl, g_atl);
    cudaGetSymbolAddress((void**)&hh,  g_hh);
    cudaGetSymbolAddress((void**)&hl,  g_hl);
    cudaGetSymbolAddress((void**)&bh,  g_bh);

    cudaFuncSetAttribute(tc_gemm<2>, cudaFuncAttributeMaxDynamicSharedMemorySize, GS_TOTAL);
    cudaFuncSetAttribute(tc_gemm<3>, cudaFuncAttributeMaxDynamicSharedMemorySize, GS_TOTAL);
    cudaFuncSetAttribute(tc_gemm<4>, cudaFuncAttributeMaxDynamicSharedMemorySize, GS_TOTAL);
    cudaFuncSetAttribute(flash_tc, cudaFuncAttributeMaxDynamicSharedMemorySize, F_TOTAL);

    ln_kernel<<<ROWS, 256>>>(x, ln1_g, ln1_b, ah, al);
    convT_kernel<<<dim3(3 * Ww / 32, Ww / 32), dim3(32, 8)>>>(qkv_w, bh, Ww, 3 * Ww);
    tc_gemm<3><<<dim3(3 * Ww / 256, ROWS / 128), 256, GS_TOTAL>>>(
        ah, al, bh, qkv_b, nullptr, nullptr, qh, ql, ROWS, 3 * Ww, Ww);
    flash_tc<<<dim3(Nn / 128, Hh, Bb), 256, F_TOTAL>>>(qh, ql, ath, atl);
    convT_kernel<<<dim3(Ww / 32, Ww / 32), dim3(32, 8)>>>(proj_w, bh, Ww, Ww);
    tc_gemm<2><<<dim3(Ww / 256, ROWS / 128), 256, GS_TOTAL>>>(
        ath, atl, bh, proj_b, x, x1, nullptr, nullptr, ROWS, Ww, Ww);
    ln_kernel<<<ROWS, 256>>>(x1, ln2_g, ln2_b, ah, al);
    convT_kernel<<<dim3(4 * Ww / 32, Ww / 32), dim3(32, 8)>>>(fc_w, bh, Ww, 4 * Ww);
    tc_gemm<4><<<dim3(4 * Ww / 256, ROWS / 128), 256, GS_TOTAL>>>(
        ah, al, bh, fc_b, nullptr, nullptr, hh, hl, ROWS, 4 * Ww, Ww);
    convT_kernel<<<dim3(Ww / 32, 4 * Ww / 32), dim3(32, 8)>>>(fc2_w, bh, 4 * Ww, Ww);
    tc_gemm<2><<<dim3(Ww / 256, ROWS / 128), 256, GS_TOTAL>>>(
        hh, hl, bh, fc2_b, x1, out, nullptr, nullptr, ROWS, Ww, 4 * Ww);
}

// round 7
// speedup vs baseline: 6.4170x; 1.4732x over previous
#include <cuda_runtime.h>
#include <cuda_fp16.h>
#include <math.h>
#include <stdint.h>

// Problem constants
#define Bb 2
#define Nn 2048
#define Ww 1024
#define Hh 16
#define HDd 64
#define ROWS (Bb * Nn)   // 4096

// ----------------------------------------------------------------------------
// Scratch buffers
// ----------------------------------------------------------------------------
__device__ float g_x1[ROWS * Ww];            // post-attention residual (fp32)
__device__ __half g_ah[ROWS * Ww];           // ln output (fp16)
__device__ __half g_qh[ROWS * 3 * Ww];       // qkv hi (q pre-scaled)
__device__ __half g_ql[ROWS * 3 * Ww];       // qkv lo (for flash Q split)
__device__ __half g_ath[ROWS * Ww];          // attention out (fp16)
__device__ __half g_hh[ROWS * 4 * Ww];       // gelu out (fp16)
__device__ __half g_bh[4 * Ww * Ww];         // weight fp16, [N,K] transposed

#define SWZ128(off) ((off) ^ (((off) >> 3) & 0x70))

__device__ __forceinline__ uint32_t smem_u32(const void* p) {
    uint32_t a;
    asm("{ .reg .u64 t; cvta.to.shared.u64 t, %1; cvt.u32.u64 %0, t; }" : "=r"(a) : "l"(p));
    return a;
}
__device__ __forceinline__ void cp16(uint32_t saddr, const void* g) {
    asm volatile("cp.async.cg.shared.global [%0], [%1], 16;" :: "r"(saddr), "l"(g));
}
#define CP_COMMIT() asm volatile("cp.async.commit_group;" ::: "memory")
#define CP_WAIT2()  asm volatile("cp.async.wait_group 2;" ::: "memory")
#define CP_WAIT1()  asm volatile("cp.async.wait_group 1;" ::: "memory")
#define CP_WAIT0()  asm volatile("cp.async.wait_group 0;" ::: "memory")

__device__ __forceinline__ void ldsm_x4(uint32_t& a0, uint32_t& a1, uint32_t& a2, uint32_t& a3,
                                        uint32_t addr) {
    asm volatile("ldmatrix.sync.aligned.m8n8.x4.shared.b16 {%0,%1,%2,%3}, [%4];"
                 : "=r"(a0), "=r"(a1), "=r"(a2), "=r"(a3) : "r"(addr));
}
__device__ __forceinline__ void ldsm_x2(uint32_t& b0, uint32_t& b1, uint32_t addr) {
    asm volatile("ldmatrix.sync.aligned.m8n8.x2.shared.b16 {%0,%1}, [%2];"
                 : "=r"(b0), "=r"(b1) : "r"(addr));
}
__device__ __forceinline__ void ldsm_x2t(uint32_t& b0, uint32_t& b1, uint32_t addr) {
    asm volatile("ldmatrix.sync.aligned.m8n8.x2.trans.shared.b16 {%0,%1}, [%2];"
                 : "=r"(b0), "=r"(b1) : "r"(addr));
}
__device__ __forceinline__ void mma_f16(float* c,
                                        uint32_t a0, uint32_t a1, uint32_t a2, uint32_t a3,
                                        uint32_t b0, uint32_t b1) {
    asm volatile(
        "mma.sync.aligned.m16n8k16.row.col.f32.f16.f16.f32 "
        "{%0,%1,%2,%3}, {%4,%5,%6,%7}, {%8,%9}, {%0,%1,%2,%3};"
        : "+f"(c[0]), "+f"(c[1]), "+f"(c[2]), "+f"(c[3])
        : "r"(a0), "r"(a1), "r"(a2), "r"(a3), "r"(b0), "r"(b1));
}
__device__ __forceinline__ uint32_t pack_h2(float a, float b) {
    __half2 t = __floats2half2_rn(a, b);
    return *(uint32_t*)&t;
}
__device__ __forceinline__ float gelu_exact(float v) {
    return 0.5f * v * (1.0f + erff(v * 0.70710678118654752f));
}

// ----------------------------------------------------------------------------
// transpose-convert: W fp32 [K,N] -> fp16 [N,K]
// ----------------------------------------------------------------------------
__global__ void convT_kernel(const float* __restrict__ w, __half* __restrict__ hi,
                             int K, int N) {
    __shared__ float t[32][33];
    int n0 = blockIdx.x * 32, k0 = blockIdx.y * 32;
    int tx = threadIdx.x, ty = threadIdx.y;   // 32 x 8
    #pragma unroll
    for (int i = 0; i < 32; i += 8)
        t[ty + i][tx] = w[(size_t)(k0 + ty + i) * N + n0 + tx];
    __syncthreads();
    #pragma unroll
    for (int i = 0; i < 32; i += 8)
        hi[(size_t)(n0 + ty + i) * K + k0 + tx] = __float2half(t[tx][ty + i]);
}

// ----------------------------------------------------------------------------
// cp.async 3-stage mma.sync fp16 GEMM (single pass, fp16 x fp16).
// C[M,N] = A[M,K] @ B^T (B stored [N,K]).
// CTA 128x256, K chunk 64, 8 warps (2x4), warp tile 64x64.
// EPI: 2 = bias+residual -> fp32; 3 = bias,q-scale -> fp16 hi/lo;
//      4 = bias+gelu -> fp16
// ----------------------------------------------------------------------------
#define GS_A 0
#define GS_B 16384
#define GS_STAGE 49152
#define GS_TOTAL (3 * GS_STAGE)   // 144 KB

template <int EPI>
__global__ void __launch_bounds__(256)
tc_gemm(const __half* __restrict__ A, const __half* __restrict__ B,
        const float* __restrict__ bias, const float* __restrict__ res,
        float* __restrict__ Cf, __half* __restrict__ Ch, __half* __restrict__ Cl,
        int M, int N, int K) {
    extern __shared__ char smem[];
    uint32_t sb = smem_u32(smem);
    const int tid = threadIdx.x, wid = tid >> 5, lid = tid & 31;
    const int bm = blockIdx.y * 128, bn = blockIdx.x * 256;
    const int wm = (wid & 1) * 64;
    const int wn = (wid >> 1) * 64;

    float acc[4][8][4];
    #pragma unroll
    for (int i = 0; i < 4; i++)
        #pragma unroll
        for (int j = 0; j < 8; j++)
            #pragma unroll
            for (int r = 0; r < 4; r++) acc[i][j][r] = 0.f;

    const int a_r  = lid & 15;
    const int a_kb = (lid >> 4) * 16;
    const int b_r  = lid & 7;
    const int b_kb = ((lid >> 3) & 1) * 16;

    const int nchunk = K >> 6;
    #define G_LOAD(ck, s) do { \
        const int _k0 = (ck) << 6; \
        uint32_t _dst = sb + (s) * GS_STAGE; \
        _Pragma("unroll") \
        for (int _i = 0; _i < 4; _i++) { \
            int _idx = _i * 256 + tid; \
            int _r = _idx >> 3, _c = (_idx & 7) * 16; \
            uint32_t _so = SWZ128(_r * 128 + _c); \
            cp16(_dst + GS_A + _so, (const char*)(A + (size_t)(bm + _r) * K + _k0) + _c); \
        } \
        _Pragma("unroll") \
        for (int _i = 0; _i < 8; _i++) { \
            int _idx = _i * 256 + tid; \
            int _r = _idx >> 3, _c = (_idx & 7) * 16; \
            uint32_t _so = SWZ128(_r * 128 + _c); \
            cp16(_dst + GS_B + _so, (const char*)(B + (size_t)(bn + _r) * K + _k0) + _c); \
        } \
        CP_COMMIT(); \
    } while (0)

    G_LOAD(0, 0);
    G_LOAD(1, 1);
    for (int ck = 0; ck < nchunk; ck++) {
        if (ck + 2 < nchunk) { G_LOAD(ck + 2, (ck + 2) % 3); CP_WAIT2(); }
        else if (ck + 1 < nchunk) CP_WAIT1();
        else CP_WAIT0();
        __syncthreads();
        uint32_t stg = sb + (ck % 3) * GS_STAGE;
        #pragma unroll
        for (int ks = 0; ks < 4; ks++) {
            uint32_t a[4][4];
            #pragma unroll
            for (int i = 0; i < 4; i++) {
                uint32_t off = SWZ128((wm + i * 16 + a_r) * 128 + ks * 32 + a_kb);
                ldsm_x4(a[i][0], a[i][1], a[i][2], a[i][3], stg + GS_A + off);
            }
            #pragma unroll
            for (int j = 0; j < 8; j++) {
                uint32_t b0, b1;
                uint32_t off = SWZ128((wn + j * 8 + b_r) * 128 + ks * 32 + b_kb);
                ldsm_x2(b0, b1, stg + GS_B + off);
                #pragma unroll
                for (int i = 0; i < 4; i++)
                    mma_f16(acc[i][j], a[i][0], a[i][1], a[i][2], a[i][3], b0, b1);
            }
        }
        __syncthreads();
    }
    #undef G_LOAD

    const int er = lid >> 2;
    const int ec = (lid & 3) * 2;
    #pragma unroll
    for (int i = 0; i < 4; i++) {
        #pragma unroll
        for (int j = 0; j < 8; j++) {
            int col = bn + wn + j * 8 + ec;
            float2 bi = *(const float2*)(bias + col);
            #pragma unroll
            for (int half = 0; half < 2; half++) {
                int row = bm + wm + i * 16 + er + half * 8;
                float ox = acc[i][j][half * 2 + 0] + bi.x;
                float oy = acc[i][j][half * 2 + 1] + bi.y;
                if (EPI == 2) {
                    float2 rv = *(const float2*)(res + (size_t)row * N + col);
                    float2 o = make_float2(ox + rv.x, oy + rv.y);
                    *(float2*)(Cf + (size_t)row * N + col) = o;
                } else if (EPI == 3) {
                    float s = ((col % 192) < 64) ? 0.125f : 1.0f;
                    ox *= s; oy *= s;
                    __half hx = __float2half(ox), hy = __float2half(oy);
                    *(uint32_t*)(Ch + (size_t)row * N + col) =
                        pack_h2(__half2float(hx), __half2float(hy));
                    *(uint32_t*)(Cl + (size_t)row * N + col) =
                        pack_h2(ox - __half2float(hx), oy - __half2float(hy));
                } else {   // EPI == 4
                    ox = gelu_exact(ox); oy = gelu_exact(oy);
                    *(uint32_t*)(Ch + (size_t)row * N + col) = pack_h2(ox, oy);
                }
            }
        }
    }
}

// ----------------------------------------------------------------------------
// LayerNorm -> fp16 output
// ----------------------------------------------------------------------------
__global__ void ln_kernel(const float* __restrict__ x, const float* __restrict__ g,
                          const float* __restrict__ beta, __half* __restrict__ yh) {
    int row = blockIdx.x, tid = threadIdx.x;
    const float* xr = x + (size_t)row * Ww;
    float4 v = *(const float4*)(xr + tid * 4);
    float s = v.x + v.y + v.z + v.w;
    float ss = v.x * v.x + v.y * v.y + v.z * v.z + v.w * v.w;
    #pragma unroll
    for (int off = 16; off; off >>= 1) {
        s  += __shfl_xor_sync(0xffffffffu, s, off);
        ss += __shfl_xor_sync(0xffffffffu, ss, off);
    }
    __shared__ float sb[8], sq[8];
    if ((tid & 31) == 0) { sb[tid >> 5] = s; sq[tid >> 5] = ss; }
    __syncthreads();
    if (tid < 32) {
        float a  = (tid < 8) ? sb[tid] : 0.f;
        float b2 = (tid < 8) ? sq[tid] : 0.f;
        #pragma unroll
        for (int off = 4; off; off >>= 1) {
            a  += __shfl_xor_sync(0xffffffffu, a, off);
            b2 += __shfl_xor_sync(0xffffffffu, b2, off);
        }
        if (tid == 0) { sb[0] = a; sq[0] = b2; }
    }
    __syncthreads();
    float mean = sb[0] * (1.f / Ww);
    float var  = sq[0] * (1.f / Ww) - mean * mean;
    float rstd = rsqrtf(var + 1e-5f);
    float4 gv = *(const float4*)(g + tid * 4);
    float4 bv = *(const float4*)(beta + tid * 4);
    float o0 = (v.x - mean) * rstd * gv.x + bv.x;
    float o1 = (v.y - mean) * rstd * gv.y + bv.y;
    float o2 = (v.z - mean) * rstd * gv.z + bv.z;
    float o3 = (v.w - mean) * rstd * gv.w + bv.w;
    size_t base = (size_t)row * Ww + tid * 4;
    *(uint32_t*)(yh + base)     = pack_h2(o0, o1);
    *(uint32_t*)(yh + base + 2) = pack_h2(o2, o3);
}

// ----------------------------------------------------------------------------
// Tensor-core flash attention, fp16.
// Q split hi/lo (2-pass S); K, V, P single fp16 (1-pass P@V). fp16 out (hi only).
// ----------------------------------------------------------------------------
#define F_QH 0
#define F_QL 16384
#define F_ST 32768
#define F_K  0
#define F_V  8192
#define F_STAGE 16384
#define F_TOTAL (F_ST + 3 * F_STAGE)

__global__ void __launch_bounds__(256)
flash_tc(const __half* __restrict__ qh, const __half* __restrict__ ql,
         __half* __restrict__ oh) {
    extern __shared__ char smem[];
    uint32_t sbm = smem_u32(smem);
    const int tid = threadIdx.x, wid = tid >> 5, lid = tid & 31;
    const int qt = blockIdx.x, h = blockIdx.y, b = blockIdx.z;
    const int wm = wid * 16;

    const size_t hcol = (size_t)h * 192;

    #pragma unroll
    for (int i = 0; i < 4; i++) {
        int idx = i * 256 + tid;
        int r = idx >> 3, c = (idx & 7) * 16;
        uint32_t so = SWZ128(r * 128 + c);
        const char* gq = (const char*)(qh + (size_t)(b * Nn + qt * 128 + r) * (3 * Ww) + hcol) + c;
        const char* gl = (const char*)(ql + (size_t)(b * Nn + qt * 128 + r) * (3 * Ww) + hcol) + c;
        cp16(sbm + F_QH + so, gq);
        cp16(sbm + F_QL + so, gl);
    }
    CP_COMMIT();

    #define F_LOAD(kt, s) do { \
        uint32_t _dst = sbm + F_ST + (s) * F_STAGE; \
        _Pragma("unroll") \
        for (int _i = 0; _i < 2; _i++) { \
            int _idx = _i * 256 + tid; \
            int _r = _idx >> 3, _c = (_idx & 7) * 16; \
            uint32_t _so = SWZ128(_r * 128 + _c); \
            size_t _row = (size_t)(b * Nn + (kt) * 64 + _r) * (3 * Ww) + hcol; \
            cp16(_dst + F_K + _so, (const char*)(qh + _row + 64) + _c); \
            cp16(_dst + F_V + _so, (const char*)(qh + _row + 128) + _c); \
        } \
        CP_COMMIT(); \
    } while (0)

    F_LOAD(0, 0);
    F_LOAD(1, 1);

    const int a_r  = lid & 15;
    const int a_kb = (lid >> 4) * 16;
    const int b_r  = lid & 7;
    const int b_kb = ((lid >> 3) & 1) * 16;

    float O[8][4];
    #pragma unroll
    for (int j = 0; j < 8; j++)
        #pragma unroll
        for (int r = 0; r < 4; r++) O[j][r] = 0.f;
    float m0 = -INFINITY, m1 = -INFINITY, l0 = 0.f, l1 = 0.f;

    const int NKT = Nn / 64;
    for (int kt = 0; kt < NKT; kt++) {
        if (kt + 2 < NKT) { F_LOAD(kt + 2, (kt + 2) % 3); CP_WAIT2(); }
        else if (kt + 1 < NKT) CP_WAIT1();
        else CP_WAIT0();
        __syncthreads();
        uint32_t stg = sbm + F_ST + (kt % 3) * F_STAGE;

        float S[8][4];
        #pragma unroll
        for (int j = 0; j < 8; j++)
            #pragma unroll
            for (int r = 0; r < 4; r++) S[j][r] = 0.f;
        #pragma unroll
        for (int ks = 0; ks < 4; ks++) {
            uint32_t bk[8][2];
            #pragma unroll
            for (int j = 0; j < 8; j++)
                ldsm_x2(bk[j][0], bk[j][1], stg + F_K + SWZ128((j * 8 + b_r) * 128 + ks * 32 + b_kb));
            #pragma unroll
            for (int pass = 0; pass < 2; pass++) {
                const uint32_t sA = sbm + (pass ? F_QL : F_QH);
                uint32_t a0, a1, a2, a3;
                ldsm_x4(a0, a1, a2, a3, sA + SWZ128((wm + a_r) * 128 + ks * 32 + a_kb));
                #pragma unroll
                for (int j = 0; j < 8; j++)
                    mma_f16(S[j], a0, a1, a2, a3, bk[j][0], bk[j][1]);
            }
        }

        float mx0 = -INFINITY, mx1 = -INFINITY;
        #pragma unroll
        for (int j = 0; j < 8; j++) {
            mx0 = fmaxf(mx0, fmaxf(S[j][0], S[j][1]));
            mx1 = fmaxf(mx1, fmaxf(S[j][2], S[j][3]));
        }
        mx0 = fmaxf(mx0, __shfl_xor_sync(0xffffffffu, mx0, 1));
        mx0 = fmaxf(mx0, __shfl_xor_sync(0xffffffffu, mx0, 2));
        mx1 = fmaxf(mx1, __shfl_xor_sync(0xffffffffu, mx1, 1));
        mx1 = fmaxf(mx1, __shfl_xor_sync(0xffffffffu, mx1, 2));
        float nm0 = fmaxf(m0, mx0), nm1 = fmaxf(m1, mx1);
        float al0 = __expf(m0 - nm0), al1 = __expf(m1 - nm1);
        float s0 = 0.f, s1 = 0.f;
        #pragma unroll
        for (int j = 0; j < 8; j++) {
            S[j][0] = __expf(S[j][0] - nm0); s0 += S[j][0];
            S[j][1] = __expf(S[j][1] - nm0); s0 += S[j][1];
            S[j][2] = __expf(S[j][2] - nm1); s1 += S[j][2];
            S[j][3] = __expf(S[j][3] - nm1); s1 += S[j][3];
        }
        s0 += __shfl_xor_sync(0xffffffffu, s0, 1);
        s0 += __shfl_xor_sync(0xffffffffu, s0, 2);
        s1 += __shfl_xor_sync(0xffffffffu, s1, 1);
        s1 += __shfl_xor_sync(0xffffffffu, s1, 2);
        l0 = l0 * al0 + s0;
        l1 = l1 * al1 + s1;
        m0 = nm0; m1 = nm1;
        #pragma unroll
        for (int j = 0; j < 8; j++) {
            O[j][0] *= al0; O[j][1] *= al0;
            O[j][2] *= al1; O[j][3] *= al1;
        }

        #pragma unroll
        for (int t = 0; t < 4; t++) {
            uint32_t ph[4];
            #pragma unroll
            for (int half = 0; half < 2; half++) {
                int j = 2 * t + half;
                ph[half * 2 + 0] = pack_h2(S[j][0], S[j][1]);
                ph[half * 2 + 1] = pack_h2(S[j][2], S[j][3]);
            }
            uint32_t vrow = t * 16 + (lid & 15);
            #pragma unroll
            for (int j = 0; j < 8; j++) {
                uint32_t off = SWZ128(vrow * 128 + j * 16);
                uint32_t v0, v1;
                ldsm_x2t(v0, v1, stg + F_V + off);
                mma_f16(O[j], ph[0], ph[1], ph[2], ph[3], v0, v1);
            }
        }
        __syncthreads();
    }
    #undef F_LOAD

    float inv0 = 1.f / l0, inv1 = 1.f / l1;
    int r0 = b * Nn + qt * 128 + wm + (lid >> 2);
    int r1 = r0 + 8;
    int cb = h * 64 + (lid & 3) * 2;
    #pragma unroll
    for (int j = 0; j < 8; j++) {
        int col = cb + j * 8;
        *(uint32_t*)(oh + (size_t)r0 * Ww + col) = pack_h2(O[j][0] * inv0, O[j][1] * inv0);
        *(uint32_t*)(oh + (size_t)r1 * Ww + col) = pack_h2(O[j][2] * inv1, O[j][3] * inv1);
    }
}

// ----------------------------------------------------------------------------
// Launcher
// ----------------------------------------------------------------------------
extern "C" void kernel_launch(void* const* d_in, const int* in_sizes, int n_in,
                              void* d_out, int out_size) {
    const float* x      = (const float*)d_in[0];
    const float* ln1_g  = (const float*)d_in[1];
    const float* ln1_b  = (const float*)d_in[2];
    const float* qkv_w  = (const float*)d_in[3];
    const float* qkv_b  = (const float*)d_in[4];
    const float* proj_w = (const float*)d_in[5];
    const float* proj_b = (const float*)d_in[6];
    const float* ln2_g  = (const float*)d_in[7];
    const float* ln2_b  = (const float*)d_in[8];
    const float* fc_w   = (const float*)d_in[9];
    const float* fc_b   = (const float*)d_in[10];
    const float* fc2_w  = (const float*)d_in[11];
    const float* fc2_b  = (const float*)d_in[12];
    float* out = (float*)d_out;

    float* x1;
    __half *ah, *qh, *ql, *ath, *hh, *bh;
    cudaGetSymbolAddress((void**)&x1,  g_x1);
    cudaGetSymbolAddress((void**)&ah,  g_ah);
    cudaGetSymbolAddress((void**)&qh,  g_qh);
    cudaGetSymbolAddress((void**)&ql,  g_ql);
    cudaGetSymbolAddress((void**)&ath, g_ath);
    cudaGetSymbolAddress((void**)&hh,  g_hh);
    cudaGetSymbolAddress((void**)&bh,  g_bh);

    cudaFuncSetAttribute(tc_gemm<2>, cudaFuncAttributeMaxDynamicSharedMemorySize, GS_TOTAL);
    cudaFuncSetAttribute(tc_gemm<3>, cudaFuncAttributeMaxDynamicSharedMemorySize, GS_TOTAL);
    cudaFuncSetAttribute(tc_gemm<4>, cudaFuncAttributeMaxDynamicSharedMemorySize, GS_TOTAL);
    cudaFuncSetAttribute(flash_tc, cudaFuncAttributeMaxDynamicSharedMemorySize, F_TOTAL);

    ln_kernel<<<ROWS, 256>>>(x, ln1_g, ln1_b, ah);
    convT_kernel<<<dim3(3 * Ww / 32, Ww / 32), dim3(32, 8)>>>(qkv_w, bh, Ww, 3 * Ww);
    tc_gemm<3><<<dim3(3 * Ww / 256, ROWS / 128), 256, GS_TOTAL>>>(
        ah, bh, qkv_b, nullptr, nullptr, qh, ql, ROWS, 3 * Ww, Ww);
    flash_tc<<<dim3(Nn / 128, Hh, Bb), 256, F_TOTAL>>>(qh, ql, ath);
    convT_kernel<<<dim3(Ww / 32, Ww / 32), dim3(32, 8)>>>(proj_w, bh, Ww, Ww);
    tc_gemm<2><<<dim3(Ww / 256, ROWS / 128), 256, GS_TOTAL>>>(
        ath, bh, proj_b, x, x1, nullptr, nullptr, ROWS, Ww, Ww);
    ln_kernel<<<ROWS, 256>>>(x1, ln2_g, ln2_b, ah);
    convT_kernel<<<dim3(4 * Ww / 32, Ww / 32), dim3(32, 8)>>>(fc_w, bh, Ww, 4 * Ww);
    tc_gemm<4><<<dim3(4 * Ww / 256, ROWS / 128), 256, GS_TOTAL>>>(
        ah, bh, fc_b, nullptr, nullptr, hh, nullptr, ROWS, 4 * Ww, Ww);
    convT_kernel<<<dim3(Ww / 32, 4 * Ww / 32), dim3(32, 8)>>>(fc2_w, bh, 4 * Ww, Ww);
    tc_gemm<2><<<dim3(Ww / 256, ROWS / 128), 256, GS_TOTAL>>>(
        hh, bh, fc2_b, x1, out, nullptr, nullptr, ROWS, Ww, 4 * Ww);
}

// round 8
// speedup vs baseline: 6.8925x; 1.0741x over previous
#include <cuda_runtime.h>
#include <cuda_fp16.h>
#include <math.h>
#include <stdint.h>

// Problem constants
#define Bb 2
#define Nn 2048
#define Ww 1024
#define Hh 16
#define HDd 64
#define ROWS (Bb * Nn)   // 4096

// ----------------------------------------------------------------------------
// Scratch buffers
// ----------------------------------------------------------------------------
__device__ float g_x1[ROWS * Ww];            // post-attention residual (fp32)
__device__ __half g_ah[ROWS * Ww];           // ln output (fp16)
__device__ __half g_qh[ROWS * 3 * Ww];       // qkv (q pre-scaled), fp16
__device__ __half g_ath[ROWS * Ww];          // attention out (fp16)
__device__ __half g_hh[ROWS * 4 * Ww];       // gelu out (fp16)
__device__ __half g_bh[4 * Ww * Ww];         // weight fp16, [N,K] transposed

#define SWZ128(off) ((off) ^ (((off) >> 3) & 0x70))

__device__ __forceinline__ uint32_t smem_u32(const void* p) {
    uint32_t a;
    asm("{ .reg .u64 t; cvta.to.shared.u64 t, %1; cvt.u32.u64 %0, t; }" : "=r"(a) : "l"(p));
    return a;
}
__device__ __forceinline__ void cp16(uint32_t saddr, const void* g) {
    asm volatile("cp.async.cg.shared.global [%0], [%1], 16;" :: "r"(saddr), "l"(g));
}
#define CP_COMMIT() asm volatile("cp.async.commit_group;" ::: "memory")
#define CP_WAIT2()  asm volatile("cp.async.wait_group 2;" ::: "memory")
#define CP_WAIT1()  asm volatile("cp.async.wait_group 1;" ::: "memory")
#define CP_WAIT0()  asm volatile("cp.async.wait_group 0;" ::: "memory")

__device__ __forceinline__ void ldsm_x4(uint32_t& a0, uint32_t& a1, uint32_t& a2, uint32_t& a3,
                                        uint32_t addr) {
    asm volatile("ldmatrix.sync.aligned.m8n8.x4.shared.b16 {%0,%1,%2,%3}, [%4];"
                 : "=r"(a0), "=r"(a1), "=r"(a2), "=r"(a3) : "r"(addr));
}
__device__ __forceinline__ void ldsm_x2(uint32_t& b0, uint32_t& b1, uint32_t addr) {
    asm volatile("ldmatrix.sync.aligned.m8n8.x2.shared.b16 {%0,%1}, [%2];"
                 : "=r"(b0), "=r"(b1) : "r"(addr));
}
__device__ __forceinline__ void ldsm_x2t(uint32_t& b0, uint32_t& b1, uint32_t addr) {
    asm volatile("ldmatrix.sync.aligned.m8n8.x2.trans.shared.b16 {%0,%1}, [%2];"
                 : "=r"(b0), "=r"(b1) : "r"(addr));
}
__device__ __forceinline__ void mma_f16(float* c,
                                        uint32_t a0, uint32_t a1, uint32_t a2, uint32_t a3,
                                        uint32_t b0, uint32_t b1) {
    asm volatile(
        "mma.sync.aligned.m16n8k16.row.col.f32.f16.f16.f32 "
        "{%0,%1,%2,%3}, {%4,%5,%6,%7}, {%8,%9}, {%0,%1,%2,%3};"
        : "+f"(c[0]), "+f"(c[1]), "+f"(c[2]), "+f"(c[3])
        : "r"(a0), "r"(a1), "r"(a2), "r"(a3), "r"(b0), "r"(b1));
}
__device__ __forceinline__ uint32_t pack_h2(float a, float b) {
    __half2 t = __floats2half2_rn(a, b);
    return *(uint32_t*)&t;
}
__device__ __forceinline__ float gelu_exact(float v) {
    return 0.5f * v * (1.0f + erff(v * 0.70710678118654752f));
}

// ----------------------------------------------------------------------------
// transpose-convert: W fp32 [K,N] -> fp16 [N,K]
// ----------------------------------------------------------------------------
__global__ void convT_kernel(const float* __restrict__ w, __half* __restrict__ hi,
                             int K, int N) {
    __shared__ float t[32][33];
    int n0 = blockIdx.x * 32, k0 = blockIdx.y * 32;
    int tx = threadIdx.x, ty = threadIdx.y;   // 32 x 8
    #pragma unroll
    for (int i = 0; i < 32; i += 8)
        t[ty + i][tx] = w[(size_t)(k0 + ty + i) * N + n0 + tx];
    __syncthreads();
    #pragma unroll
    for (int i = 0; i < 32; i += 8)
        hi[(size_t)(n0 + ty + i) * K + k0 + tx] = __float2half(t[tx][ty + i]);
}

// ----------------------------------------------------------------------------
// cp.async 3-stage mma.sync fp16 GEMM (single pass, fp16 x fp16).
// C[M,N] = A[M,K] @ B^T (B stored [N,K]).
// CTA 128x128, K chunk 64, 8 warps (2x4), warp tile 64x32. 96 KB smem -> 2 CTA/SM.
// EPI: 2 = bias+residual -> fp32; 3 = bias,q-scale -> fp16; 4 = bias+gelu -> fp16
// ----------------------------------------------------------------------------
#define GS_A 0
#define GS_B 16384
#define GS_STAGE 32768
#define GS_TOTAL (3 * GS_STAGE)   // 96 KB

template <int EPI>
__global__ void __launch_bounds__(256)
tc_gemm(const __half* __restrict__ A, const __half* __restrict__ B,
        const float* __restrict__ bias, const float* __restrict__ res,
        float* __restrict__ Cf, __half* __restrict__ Ch,
        int M, int N, int K) {
    extern __shared__ char smem[];
    uint32_t sb = smem_u32(smem);
    const int tid = threadIdx.x, wid = tid >> 5, lid = tid & 31;
    const int bm = blockIdx.y * 128, bn = blockIdx.x * 128;
    const int wm = (wid & 1) * 64;
    const int wn = (wid >> 1) * 32;

    float acc[4][4][4];
    #pragma unroll
    for (int i = 0; i < 4; i++)
        #pragma unroll
        for (int j = 0; j < 4; j++)
            #pragma unroll
            for (int r = 0; r < 4; r++) acc[i][j][r] = 0.f;

    const int a_r  = lid & 15;
    const int a_kb = (lid >> 4) * 16;
    const int b_r  = lid & 7;
    const int b_kb = ((lid >> 3) & 1) * 16;

    const int nchunk = K >> 6;
    #define G_LOAD(ck, s) do { \
        const int _k0 = (ck) << 6; \
        uint32_t _dst = sb + (s) * GS_STAGE; \
        _Pragma("unroll") \
        for (int _i = 0; _i < 4; _i++) { \
            int _idx = _i * 256 + tid; \
            int _r = _idx >> 3, _c = (_idx & 7) * 16; \
            uint32_t _so = SWZ128(_r * 128 + _c); \
            cp16(_dst + GS_A + _so, (const char*)(A + (size_t)(bm + _r) * K + _k0) + _c); \
            cp16(_dst + GS_B + _so, (const char*)(B + (size_t)(bn + _r) * K + _k0) + _c); \
        } \
        CP_COMMIT(); \
    } while (0)

    G_LOAD(0, 0);
    G_LOAD(1, 1);
    for (int ck = 0; ck < nchunk; ck++) {
        if (ck + 2 < nchunk) { G_LOAD(ck + 2, (ck + 2) % 3); CP_WAIT2(); }
        else if (ck + 1 < nchunk) CP_WAIT1();
        else CP_WAIT0();
        __syncthreads();
        uint32_t stg = sb + (ck % 3) * GS_STAGE;
        #pragma unroll
        for (int ks = 0; ks < 4; ks++) {
            uint32_t a[4][4];
            #pragma unroll
            for (int i = 0; i < 4; i++) {
                uint32_t off = SWZ128((wm + i * 16 + a_r) * 128 + ks * 32 + a_kb);
                ldsm_x4(a[i][0], a[i][1], a[i][2], a[i][3], stg + GS_A + off);
            }
            #pragma unroll
            for (int j = 0; j < 4; j++) {
                uint32_t b0, b1;
                uint32_t off = SWZ128((wn + j * 8 + b_r) * 128 + ks * 32 + b_kb);
                ldsm_x2(b0, b1, stg + GS_B + off);
                #pragma unroll
                for (int i = 0; i < 4; i++)
                    mma_f16(acc[i][j], a[i][0], a[i][1], a[i][2], a[i][3], b0, b1);
            }
        }
        __syncthreads();
    }
    #undef G_LOAD

    const int er = lid >> 2;
    const int ec = (lid & 3) * 2;
    #pragma unroll
    for (int i = 0; i < 4; i++) {
        #pragma unroll
        for (int j = 0; j < 4; j++) {
            int col = bn + wn + j * 8 + ec;
            float2 bi = *(const float2*)(bias + col);
            #pragma unroll
            for (int half = 0; half < 2; half++) {
                int row = bm + wm + i * 16 + er + half * 8;
                float ox = acc[i][j][half * 2 + 0] + bi.x;
                float oy = acc[i][j][half * 2 + 1] + bi.y;
                if (EPI == 2) {
                    float2 rv = *(const float2*)(res + (size_t)row * N + col);
                    float2 o = make_float2(ox + rv.x, oy + rv.y);
                    *(float2*)(Cf + (size_t)row * N + col) = o;
                } else {
                    if (EPI == 3) {
                        float s = ((col % 192) < 64) ? 0.125f : 1.0f;
                        ox *= s; oy *= s;
                    }
                    if (EPI == 4) { ox = gelu_exact(ox); oy = gelu_exact(oy); }
                    *(uint32_t*)(Ch + (size_t)row * N + col) = pack_h2(ox, oy);
                }
            }
        }
    }
}

// ----------------------------------------------------------------------------
// LayerNorm -> fp16 output
// ----------------------------------------------------------------------------
__global__ void ln_kernel(const float* __restrict__ x, const float* __restrict__ g,
                          const float* __restrict__ beta, __half* __restrict__ yh) {
    int row = blockIdx.x, tid = threadIdx.x;
    const float* xr = x + (size_t)row * Ww;
    float4 v = *(const float4*)(xr + tid * 4);
    float s = v.x + v.y + v.z + v.w;
    float ss = v.x * v.x + v.y * v.y + v.z * v.z + v.w * v.w;
    #pragma unroll
    for (int off = 16; off; off >>= 1) {
        s  += __shfl_xor_sync(0xffffffffu, s, off);
        ss += __shfl_xor_sync(0xffffffffu, ss, off);
    }
    __shared__ float sb[8], sq[8];
    if ((tid & 31) == 0) { sb[tid >> 5] = s; sq[tid >> 5] = ss; }
    __syncthreads();
    if (tid < 32) {
        float a  = (tid < 8) ? sb[tid] : 0.f;
        float b2 = (tid < 8) ? sq[tid] : 0.f;
        #pragma unroll
        for (int off = 4; off; off >>= 1) {
            a  += __shfl_xor_sync(0xffffffffu, a, off);
            b2 += __shfl_xor_sync(0xffffffffu, b2, off);
        }
        if (tid == 0) { sb[0] = a; sq[0] = b2; }
    }
    __syncthreads();
    float mean = sb[0] * (1.f / Ww);
    float var  = sq[0] * (1.f / Ww) - mean * mean;
    float rstd = rsqrtf(var + 1e-5f);
    float4 gv = *(const float4*)(g + tid * 4);
    float4 bv = *(const float4*)(beta + tid * 4);
    float o0 = (v.x - mean) * rstd * gv.x + bv.x;
    float o1 = (v.y - mean) * rstd * gv.y + bv.y;
    float o2 = (v.z - mean) * rstd * gv.z + bv.z;
    float o3 = (v.w - mean) * rstd * gv.w + bv.w;
    size_t base = (size_t)row * Ww + tid * 4;
    *(uint32_t*)(yh + base)     = pack_h2(o0, o1);
    *(uint32_t*)(yh + base + 2) = pack_h2(o2, o3);
}

// ----------------------------------------------------------------------------
// Tensor-core flash attention, fp16 throughout (single-pass S and PV).
// qkv layout: [token][h*192 + {q|k|v}], q pre-scaled by 0.125.
// CTA: 128 queries x one head. 8 warps. 3-stage K/V pipeline. 64 KB smem.
// ----------------------------------------------------------------------------
#define F_Q  0
#define F_ST 16384
#define F_K  0
#define F_V  8192
#define F_STAGE 16384
#define F_TOTAL (F_ST + 3 * F_STAGE)   // 64 KB

__global__ void __launch_bounds__(256)
flash_tc(const __half* __restrict__ qh, __half* __restrict__ oh) {
    extern __shared__ char smem[];
    uint32_t sbm = smem_u32(smem);
    const int tid = threadIdx.x, wid = tid >> 5, lid = tid & 31;
    const int qt = blockIdx.x, h = blockIdx.y, b = blockIdx.z;
    const int wm = wid * 16;

    const size_t hcol = (size_t)h * 192;

    #pragma unroll
    for (int i = 0; i < 4; i++) {
        int idx = i * 256 + tid;
        int r = idx >> 3, c = (idx & 7) * 16;
        uint32_t so = SWZ128(r * 128 + c);
        const char* gq = (const char*)(qh + (size_t)(b * Nn + qt * 128 + r) * (3 * Ww) + hcol) + c;
        cp16(sbm + F_Q + so, gq);
    }
    CP_COMMIT();

    #define F_LOAD(kt, s) do { \
        uint32_t _dst = sbm + F_ST + (s) * F_STAGE; \
        _Pragma("unroll") \
        for (int _i = 0; _i < 2; _i++) { \
            int _idx = _i * 256 + tid; \
            int _r = _idx >> 3, _c = (_idx & 7) * 16; \
            uint32_t _so = SWZ128(_r * 128 + _c); \
            size_t _row = (size_t)(b * Nn + (kt) * 64 + _r) * (3 * Ww) + hcol; \
            cp16(_dst + F_K + _so, (const char*)(qh + _row + 64) + _c); \
            cp16(_dst + F_V + _so, (const char*)(qh + _row + 128) + _c); \
        } \
        CP_COMMIT(); \
    } while (0)

    F_LOAD(0, 0);
    F_LOAD(1, 1);

    const int a_r  = lid & 15;
    const int a_kb = (lid >> 4) * 16;
    const int b_r  = lid & 7;
    const int b_kb = ((lid >> 3) & 1) * 16;

    float O[8][4];
    #pragma unroll
    for (int j = 0; j < 8; j++)
        #pragma unroll
        for (int r = 0; r < 4; r++) O[j][r] = 0.f;
    float m0 = -INFINITY, m1 = -INFINITY, l0 = 0.f, l1 = 0.f;

    const int NKT = Nn / 64;
    for (int kt = 0; kt < NKT; kt++) {
        if (kt + 2 < NKT) { F_LOAD(kt + 2, (kt + 2) % 3); CP_WAIT2(); }
        else if (kt + 1 < NKT) CP_WAIT1();
        else CP_WAIT0();
        __syncthreads();
        uint32_t stg = sbm + F_ST + (kt % 3) * F_STAGE;

        float S[8][4];
        #pragma unroll
        for (int j = 0; j < 8; j++)
            #pragma unroll
            for (int r = 0; r < 4; r++) S[j][r] = 0.f;
        #pragma unroll
        for (int ks = 0; ks < 4; ks++) {
            uint32_t a0, a1, a2, a3;
            ldsm_x4(a0, a1, a2, a3, sbm + F_Q + SWZ128((wm + a_r) * 128 + ks * 32 + a_kb));
            #pragma unroll
            for (int j = 0; j < 8; j++) {
                uint32_t b0, b1;
                ldsm_x2(b0, b1, stg + F_K + SWZ128((j * 8 + b_r) * 128 + ks * 32 + b_kb));
                mma_f16(S[j], a0, a1, a2, a3, b0, b1);
            }
        }

        float mx0 = -INFINITY, mx1 = -INFINITY;
        #pragma unroll
        for (int j = 0; j < 8; j++) {
            mx0 = fmaxf(mx0, fmaxf(S[j][0], S[j][1]));
            mx1 = fmaxf(mx1, fmaxf(S[j][2], S[j][3]));
        }
        mx0 = fmaxf(mx0, __shfl_xor_sync(0xffffffffu, mx0, 1));
        mx0 = fmaxf(mx0, __shfl_xor_sync(0xffffffffu, mx0, 2));
        mx1 = fmaxf(mx1, __shfl_xor_sync(0xffffffffu, mx1, 1));
        mx1 = fmaxf(mx1, __shfl_xor_sync(0xffffffffu, mx1, 2));
        float nm0 = fmaxf(m0, mx0), nm1 = fmaxf(m1, mx1);
        float al0 = __expf(m0 - nm0), al1 = __expf(m1 - nm1);
        float s0 = 0.f, s1 = 0.f;
        #pragma unroll
        for (int j = 0; j < 8; j++) {
            S[j][0] = __expf(S[j][0] - nm0); s0 += S[j][0];
            S[j][1] = __expf(S[j][1] - nm0); s0 += S[j][1];
            S[j][2] = __expf(S[j][2] - nm1); s1 += S[j][2];
            S[j][3] = __expf(S[j][3] - nm1); s1 += S[j][3];
        }
        s0 += __shfl_xor_sync(0xffffffffu, s0, 1);
        s0 += __shfl_xor_sync(0xffffffffu, s0, 2);
        s1 += __shfl_xor_sync(0xffffffffu, s1, 1);
        s1 += __shfl_xor_sync(0xffffffffu, s1, 2);
        l0 = l0 * al0 + s0;
        l1 = l1 * al1 + s1;
        m0 = nm0; m1 = nm1;
        #pragma unroll
        for (int j = 0; j < 8; j++) {
            O[j][0] *= al0; O[j][1] *= al0;
            O[j][2] *= al1; O[j][3] *= al1;
        }

        #pragma unroll
        for (int t = 0; t < 4; t++) {
            uint32_t ph[4];
            #pragma unroll
            for (int half = 0; half < 2; half++) {
                int j = 2 * t + half;
                ph[half * 2 + 0] = pack_h2(S[j][0], S[j][1]);
                ph[half * 2 + 1] = pack_h2(S[j][2], S[j][3]);
            }
            uint32_t vrow = t * 16 + (lid & 15);
            #pragma unroll
            for (int j = 0; j < 8; j++) {
                uint32_t off = SWZ128(vrow * 128 + j * 16);
                uint32_t v0, v1;
                ldsm_x2t(v0, v1, stg + F_V + off);
                mma_f16(O[j], ph[0], ph[1], ph[2], ph[3], v0, v1);
            }
        }
        __syncthreads();
    }
    #undef F_LOAD

    float inv0 = 1.f / l0, inv1 = 1.f / l1;
    int r0 = b * Nn + qt * 128 + wm + (lid >> 2);
    int r1 = r0 + 8;
    int cb = h * 64 + (lid & 3) * 2;
    #pragma unroll
    for (int j = 0; j < 8; j++) {
        int col = cb + j * 8;
        *(uint32_t*)(oh + (size_t)r0 * Ww + col) = pack_h2(O[j][0] * inv0, O[j][1] * inv0);
        *(uint32_t*)(oh + (size_t)r1 * Ww + col) = pack_h2(O[j][2] * inv1, O[j][3] * inv1);
    }
}

// ----------------------------------------------------------------------------
// Launcher
// ----------------------------------------------------------------------------
extern "C" void kernel_launch(void* const* d_in, const int* in_sizes, int n_in,
                              void* d_out, int out_size) {
    const float* x      = (const float*)d_in[0];
    const float* ln1_g  = (const float*)d_in[1];
    const float* ln1_b  = (const float*)d_in[2];
    const float* qkv_w  = (const float*)d_in[3];
    const float* qkv_b  = (const float*)d_in[4];
    const float* proj_w = (const float*)d_in[5];
    const float* proj_b = (const float*)d_in[6];
    const float* ln2_g  = (const float*)d_in[7];
    const float* ln2_b  = (const float*)d_in[8];
    const float* fc_w   = (const float*)d_in[9];
    const float* fc_b   = (const float*)d_in[10];
    const float* fc2_w  = (const float*)d_in[11];
    const float* fc2_b  = (const float*)d_in[12];
    float* out = (float*)d_out;

    float* x1;
    __half *ah, *qh, *ath, *hh, *bh;
    cudaGetSymbolAddress((void**)&x1,  g_x1);
    cudaGetSymbolAddress((void**)&ah,  g_ah);
    cudaGetSymbolAddress((void**)&qh,  g_qh);
    cudaGetSymbolAddress((void**)&ath, g_ath);
    cudaGetSymbolAddress((void**)&hh,  g_hh);
    cudaGetSymbolAddress((void**)&bh,  g_bh);

    cudaFuncSetAttribute(tc_gemm<2>, cudaFuncAttributeMaxDynamicSharedMemorySize, GS_TOTAL);
    cudaFuncSetAttribute(tc_gemm<3>, cudaFuncAttributeMaxDynamicSharedMemorySize, GS_TOTAL);
    cudaFuncSetAttribute(tc_gemm<4>, cudaFuncAttributeMaxDynamicSharedMemorySize, GS_TOTAL);
    cudaFuncSetAttribute(flash_tc, cudaFuncAttributeMaxDynamicSharedMemorySize, F_TOTAL);

    ln_kernel<<<ROWS, 256>>>(x, ln1_g, ln1_b, ah);
    convT_kernel<<<dim3(3 * Ww / 32, Ww / 32), dim3(32, 8)>>>(qkv_w, bh, Ww, 3 * Ww);
    tc_gemm<3><<<dim3(3 * Ww / 128, ROWS / 128), 256, GS_TOTAL>>>(
        ah, bh, qkv_b, nullptr, nullptr, qh, ROWS, 3 * Ww, Ww);
    flash_tc<<<dim3(Nn / 128, Hh, Bb), 256, F_TOTAL>>>(qh, ath);
    convT_kernel<<<dim3(Ww / 32, Ww / 32), dim3(32, 8)>>>(proj_w, bh, Ww, Ww);
    tc_gemm<2><<<dim3(Ww / 128, ROWS / 128), 256, GS_TOTAL>>>(
        ath, bh, proj_b, x, x1, nullptr, ROWS, Ww, Ww);
    ln_kernel<<<ROWS, 256>>>(x1, ln2_g, ln2_b, ah);
    convT_kernel<<<dim3(4 * Ww / 32, Ww / 32), dim3(32, 8)>>>(fc_w, bh, Ww, 4 * Ww);
    tc_gemm<4><<<dim3(4 * Ww / 128, ROWS / 128), 256, GS_TOTAL>>>(
        ah, bh, fc_b, nullptr, nullptr, hh, ROWS, 4 * Ww, Ww);
    convT_kernel<<<dim3(Ww / 32, 4 * Ww / 32), dim3(32, 8)>>>(fc2_w, bh, 4 * Ww, Ww);
    tc_gemm<2><<<dim3(Ww / 128, ROWS / 128), 256, GS_TOTAL>>>(
        hh, bh, fc2_b, x1, out, nullptr, ROWS, Ww, 4 * Ww);
}

// round 9
// speedup vs baseline: 7.7636x; 1.1264x over previous
#include <cuda_runtime.h>
#include <cuda_fp16.h>
#include <math.h>
#include <stdint.h>

// Problem constants
#define Bb 2
#define Nn 2048
#define Ww 1024
#define Hh 16
#define HDd 64
#define ROWS (Bb * Nn)   // 4096

// ----------------------------------------------------------------------------
// Scratch buffers
// ----------------------------------------------------------------------------
__device__ float g_x1[ROWS * Ww];            // post-attention residual (fp32)
__device__ __half g_ah[ROWS * Ww];           // ln output (fp16)
__device__ __half g_qh[ROWS * 3 * Ww];       // qkv (q pre-scaled), fp16
__device__ __half g_ath[ROWS * Ww];          // attention out (fp16)
__device__ __half g_hh[ROWS * 4 * Ww];       // gelu out (fp16)
__device__ __half g_bh[4 * Ww * Ww];         // weight fp16, [N,K] transposed

#define SWZ128(off) ((off) ^ (((off) >> 3) & 0x70))

__device__ __forceinline__ uint32_t smem_u32(const void* p) {
    uint32_t a;
    asm("{ .reg .u64 t; cvta.to.shared.u64 t, %1; cvt.u32.u64 %0, t; }" : "=r"(a) : "l"(p));
    return a;
}
__device__ __forceinline__ void cp16(uint32_t saddr, const void* g) {
    asm volatile("cp.async.cg.shared.global [%0], [%1], 16;" :: "r"(saddr), "l"(g));
}
#define CP_COMMIT() asm volatile("cp.async.commit_group;" ::: "memory")
#define CP_WAIT2()  asm volatile("cp.async.wait_group 2;" ::: "memory")
#define CP_WAIT1()  asm volatile("cp.async.wait_group 1;" ::: "memory")
#define CP_WAIT0()  asm volatile("cp.async.wait_group 0;" ::: "memory")

__device__ __forceinline__ void ldsm_x4(uint32_t& a0, uint32_t& a1, uint32_t& a2, uint32_t& a3,
                                        uint32_t addr) {
    asm volatile("ldmatrix.sync.aligned.m8n8.x4.shared.b16 {%0,%1,%2,%3}, [%4];"
                 : "=r"(a0), "=r"(a1), "=r"(a2), "=r"(a3) : "r"(addr));
}
__device__ __forceinline__ void ldsm_x4t(uint32_t& a0, uint32_t& a1, uint32_t& a2, uint32_t& a3,
                                         uint32_t addr) {
    asm volatile("ldmatrix.sync.aligned.m8n8.x4.trans.shared.b16 {%0,%1,%2,%3}, [%4];"
                 : "=r"(a0), "=r"(a1), "=r"(a2), "=r"(a3) : "r"(addr));
}
__device__ __forceinline__ void mma_f16(float* c,
                                        uint32_t a0, uint32_t a1, uint32_t a2, uint32_t a3,
                                        uint32_t b0, uint32_t b1) {
    asm volatile(
        "mma.sync.aligned.m16n8k16.row.col.f32.f16.f16.f32 "
        "{%0,%1,%2,%3}, {%4,%5,%6,%7}, {%8,%9}, {%0,%1,%2,%3};"
        : "+f"(c[0]), "+f"(c[1]), "+f"(c[2]), "+f"(c[3])
        : "r"(a0), "r"(a1), "r"(a2), "r"(a3), "r"(b0), "r"(b1));
}
__device__ __forceinline__ uint32_t pack_h2(float a, float b) {
    __half2 t = __floats2half2_rn(a, b);
    return *(uint32_t*)&t;
}
__device__ __forceinline__ float gelu_exact(float v) {
    return 0.5f * v * (1.0f + erff(v * 0.70710678118654752f));
}

// ----------------------------------------------------------------------------
// transpose-convert: W fp32 [K,N] -> fp16 [N,K]
// ----------------------------------------------------------------------------
__global__ void convT_kernel(const float* __restrict__ w, __half* __restrict__ hi,
                             int K, int N) {
    __shared__ float t[32][33];
    int n0 = blockIdx.x * 32, k0 = blockIdx.y * 32;
    int tx = threadIdx.x, ty = threadIdx.y;   // 32 x 8
    #pragma unroll
    for (int i = 0; i < 32; i += 8)
        t[ty + i][tx] = w[(size_t)(k0 + ty + i) * N + n0 + tx];
    __syncthreads();
    #pragma unroll
    for (int i = 0; i < 32; i += 8)
        hi[(size_t)(n0 + ty + i) * K + k0 + tx] = __float2half(t[tx][ty + i]);
}

// ----------------------------------------------------------------------------
// cp.async 3-stage mma.sync fp16 GEMM (single pass, fp16 x fp16).
// C[M,N] = A[M,K] @ B^T (B stored [N,K]).
// CTA 128x128, K chunk 64, 8 warps (2x4), warp tile 64x32. 96 KB smem, 2 CTA/SM.
// EPI: 2 = bias+residual -> fp32; 3 = bias,q-scale -> fp16; 4 = bias+gelu -> fp16
// ----------------------------------------------------------------------------
#define GS_A 0
#define GS_B 16384
#define GS_STAGE 32768
#define GS_TOTAL (3 * GS_STAGE)   // 96 KB

template <int EPI>
__global__ void __launch_bounds__(256, 2)
tc_gemm(const __half* __restrict__ A, const __half* __restrict__ B,
        const float* __restrict__ bias, const float* __restrict__ res,
        float* __restrict__ Cf, __half* __restrict__ Ch,
        int M, int N, int K) {
    extern __shared__ char smem[];
    uint32_t sb = smem_u32(smem);
    const int tid = threadIdx.x, wid = tid >> 5, lid = tid & 31;
    const int bm = blockIdx.y * 128, bn = blockIdx.x * 128;
    const int wm = (wid & 1) * 64;
    const int wn = (wid >> 1) * 32;

    float acc[4][4][4];
    #pragma unroll
    for (int i = 0; i < 4; i++)
        #pragma unroll
        for (int j = 0; j < 4; j++)
            #pragma unroll
            for (int r = 0; r < 4; r++) acc[i][j][r] = 0.f;

    const int a_r  = lid & 15;
    const int a_kb = (lid >> 4) * 16;
    // x4 B layout: groups g=lid>>3: t0 rows j16+(lid&7) kb0, t1 same rows kb16,
    // t2 rows j16+8.. kb0, t3 rows +8 kb16
    const int b_row = ((lid >> 4) & 1) * 8 + (lid & 7);
    const int b_kb  = ((lid >> 3) & 1) * 16;

    const int nchunk = K >> 6;
    #define G_LOAD(ck, s) do { \
        const int _k0 = (ck) << 6; \
        uint32_t _dst = sb + (s) * GS_STAGE; \
        _Pragma("unroll") \
        for (int _i = 0; _i < 4; _i++) { \
            int _idx = _i * 256 + tid; \
            int _r = _idx >> 3, _c = (_idx & 7) * 16; \
            uint32_t _so = SWZ128(_r * 128 + _c); \
            cp16(_dst + GS_A + _so, (const char*)(A + (size_t)(bm + _r) * K + _k0) + _c); \
            cp16(_dst + GS_B + _so, (const char*)(B + (size_t)(bn + _r) * K + _k0) + _c); \
        } \
        CP_COMMIT(); \
    } while (0)

    G_LOAD(0, 0);
    G_LOAD(1, 1);
    for (int ck = 0; ck < nchunk; ck++) {
        if (ck + 2 < nchunk) { G_LOAD(ck + 2, (ck + 2) % 3); CP_WAIT2(); }
        else if (ck + 1 < nchunk) CP_WAIT1();
        else CP_WAIT0();
        __syncthreads();
        uint32_t stg = sb + (ck % 3) * GS_STAGE;
        #pragma unroll
        for (int ks = 0; ks < 4; ks++) {
            uint32_t a[4][4];
            #pragma unroll
            for (int i = 0; i < 4; i++) {
                uint32_t off = SWZ128((wm + i * 16 + a_r) * 128 + ks * 32 + a_kb);
                ldsm_x4(a[i][0], a[i][1], a[i][2], a[i][3], stg + GS_A + off);
            }
            #pragma unroll
            for (int jp = 0; jp < 2; jp++) {
                uint32_t b0, b1, b2, b3;
                uint32_t off = SWZ128((wn + jp * 16 + b_row) * 128 + ks * 32 + b_kb);
                ldsm_x4(b0, b1, b2, b3, stg + GS_B + off);
                #pragma unroll
                for (int i = 0; i < 4; i++) {
                    mma_f16(acc[i][2 * jp + 0], a[i][0], a[i][1], a[i][2], a[i][3], b0, b1);
                    mma_f16(acc[i][2 * jp + 1], a[i][0], a[i][1], a[i][2], a[i][3], b2, b3);
                }
            }
        }
        __syncthreads();
    }
    #undef G_LOAD

    const int er = lid >> 2;
    const int ec = (lid & 3) * 2;
    #pragma unroll
    for (int i = 0; i < 4; i++) {
        #pragma unroll
        for (int j = 0; j < 4; j++) {
            int col = bn + wn + j * 8 + ec;
            float2 bi = *(const float2*)(bias + col);
            #pragma unroll
            for (int half = 0; half < 2; half++) {
                int row = bm + wm + i * 16 + er + half * 8;
                float ox = acc[i][j][half * 2 + 0] + bi.x;
                float oy = acc[i][j][half * 2 + 1] + bi.y;
                if (EPI == 2) {
                    float2 rv = *(const float2*)(res + (size_t)row * N + col);
                    float2 o = make_float2(ox + rv.x, oy + rv.y);
                    *(float2*)(Cf + (size_t)row * N + col) = o;
                } else {
                    if (EPI == 3) {
                        float s = ((col % 192) < 64) ? 0.125f : 1.0f;
                        ox *= s; oy *= s;
                    }
                    if (EPI == 4) { ox = gelu_exact(ox); oy = gelu_exact(oy); }
                    *(uint32_t*)(Ch + (size_t)row * N + col) = pack_h2(ox, oy);
                }
            }
        }
    }
}

// ----------------------------------------------------------------------------
// LayerNorm -> fp16 output
// ----------------------------------------------------------------------------
__global__ void ln_kernel(const float* __restrict__ x, const float* __restrict__ g,
                          const float* __restrict__ beta, __half* __restrict__ yh) {
    int row = blockIdx.x, tid = threadIdx.x;
    const float* xr = x + (size_t)row * Ww;
    float4 v = *(const float4*)(xr + tid * 4);
    float s = v.x + v.y + v.z + v.w;
    float ss = v.x * v.x + v.y * v.y + v.z * v.z + v.w * v.w;
    #pragma unroll
    for (int off = 16; off; off >>= 1) {
        s  += __shfl_xor_sync(0xffffffffu, s, off);
        ss += __shfl_xor_sync(0xffffffffu, ss, off);
    }
    __shared__ float sb[8], sq[8];
    if ((tid & 31) == 0) { sb[tid >> 5] = s; sq[tid >> 5] = ss; }
    __syncthreads();
    if (tid < 32) {
        float a  = (tid < 8) ? sb[tid] : 0.f;
        float b2 = (tid < 8) ? sq[tid] : 0.f;
        #pragma unroll
        for (int off = 4; off; off >>= 1) {
            a  += __shfl_xor_sync(0xffffffffu, a, off);
            b2 += __shfl_xor_sync(0xffffffffu, b2, off);
        }
        if (tid == 0) { sb[0] = a; sq[0] = b2; }
    }
    __syncthreads();
    float mean = sb[0] * (1.f / Ww);
    float var  = sq[0] * (1.f / Ww) - mean * mean;
    float rstd = rsqrtf(var + 1e-5f);
    float4 gv = *(const float4*)(g + tid * 4);
    float4 bv = *(const float4*)(beta + tid * 4);
    float o0 = (v.x - mean) * rstd * gv.x + bv.x;
    float o1 = (v.y - mean) * rstd * gv.y + bv.y;
    float o2 = (v.z - mean) * rstd * gv.z + bv.z;
    float o3 = (v.w - mean) * rstd * gv.w + bv.w;
    size_t base = (size_t)row * Ww + tid * 4;
    *(uint32_t*)(yh + base)     = pack_h2(o0, o1);
    *(uint32_t*)(yh + base + 2) = pack_h2(o2, o3);
}

// ----------------------------------------------------------------------------
// Tensor-core flash attention, fp16, x4 ldmatrix + skip-rescale.
// qkv layout: [token][h*192 + {q|k|v}], q pre-scaled by 0.125.
// CTA: 128 queries x one head. 8 warps. 3-stage K/V pipeline. 64 KB smem.
// ----------------------------------------------------------------------------
#define F_Q  0
#define F_ST 16384
#define F_K  0
#define F_V  8192
#define F_STAGE 16384
#define F_TOTAL (F_ST + 3 * F_STAGE)   // 64 KB

__global__ void __launch_bounds__(256, 2)
flash_tc(const __half* __restrict__ qh, __half* __restrict__ oh) {
    extern __shared__ char smem[];
    uint32_t sbm = smem_u32(smem);
    const int tid = threadIdx.x, wid = tid >> 5, lid = tid & 31;
    const int qt = blockIdx.x, h = blockIdx.y, b = blockIdx.z;
    const int wm = wid * 16;

    const size_t hcol = (size_t)h * 192;

    #pragma unroll
    for (int i = 0; i < 4; i++) {
        int idx = i * 256 + tid;
        int r = idx >> 3, c = (idx & 7) * 16;
        uint32_t so = SWZ128(r * 128 + c);
        const char* gq = (const char*)(qh + (size_t)(b * Nn + qt * 128 + r) * (3 * Ww) + hcol) + c;
        cp16(sbm + F_Q + so, gq);
    }
    CP_COMMIT();

    #define F_LOAD(kt, s) do { \
        uint32_t _dst = sbm + F_ST + (s) * F_STAGE; \
        _Pragma("unroll") \
        for (int _i = 0; _i < 2; _i++) { \
            int _idx = _i * 256 + tid; \
            int _r = _idx >> 3, _c = (_idx & 7) * 16; \
            uint32_t _so = SWZ128(_r * 128 + _c); \
            size_t _row = (size_t)(b * Nn + (kt) * 64 + _r) * (3 * Ww) + hcol; \
            cp16(_dst + F_K + _so, (const char*)(qh + _row + 64) + _c); \
            cp16(_dst + F_V + _so, (const char*)(qh + _row + 128) + _c); \
        } \
        CP_COMMIT(); \
    } while (0)

    F_LOAD(0, 0);
    F_LOAD(1, 1);

    const int a_r  = lid & 15;
    const int a_kb = (lid >> 4) * 16;
    // x4 non-trans (K): t0/t1 = rows j16+(lid&7), kb 0/16; t2/t3 = rows +8, kb 0/16
    const int k_row = ((lid >> 4) & 1) * 8 + (lid & 7);
    const int k_kb  = ((lid >> 3) & 1) * 16;
    // x4 trans (V): t0/t1 = rows t16+(lid&7)/(+8), col 0; t2/t3 = same rows, col +16
    const int v_row = ((lid >> 3) & 1) * 8 + (lid & 7);
    const int v_cb  = ((lid >> 4) & 1) * 16;

    float O[8][4];
    #pragma unroll
    for (int j = 0; j < 8; j++)
        #pragma unroll
        for (int r = 0; r < 4; r++) O[j][r] = 0.f;
    float m0 = -INFINITY, m1 = -INFINITY, l0 = 0.f, l1 = 0.f;

    const int NKT = Nn / 64;
    for (int kt = 0; kt < NKT; kt++) {
        if (kt + 2 < NKT) { F_LOAD(kt + 2, (kt + 2) % 3); CP_WAIT2(); }
        else if (kt + 1 < NKT) CP_WAIT1();
        else CP_WAIT0();
        __syncthreads();
        uint32_t stg = sbm + F_ST + (kt % 3) * F_STAGE;

        float S[8][4];
        #pragma unroll
        for (int j = 0; j < 8; j++)
            #pragma unroll
            for (int r = 0; r < 4; r++) S[j][r] = 0.f;
        #pragma unroll
        for (int ks = 0; ks < 4; ks++) {
            uint32_t a0, a1, a2, a3;
            ldsm_x4(a0, a1, a2, a3, sbm + F_Q + SWZ128((wm + a_r) * 128 + ks * 32 + a_kb));
            #pragma unroll
            for (int jp = 0; jp < 4; jp++) {
                uint32_t b0, b1, b2, b3;
                uint32_t off = SWZ128((jp * 16 + k_row) * 128 + ks * 32 + k_kb);
                ldsm_x4(b0, b1, b2, b3, stg + F_K + off);
                mma_f16(S[2 * jp + 0], a0, a1, a2, a3, b0, b1);
                mma_f16(S[2 * jp + 1], a0, a1, a2, a3, b2, b3);
            }
        }

        float mx0 = -INFINITY, mx1 = -INFINITY;
        #pragma unroll
        for (int j = 0; j < 8; j++) {
            mx0 = fmaxf(mx0, fmaxf(S[j][0], S[j][1]));
            mx1 = fmaxf(mx1, fmaxf(S[j][2], S[j][3]));
        }
        mx0 = fmaxf(mx0, __shfl_xor_sync(0xffffffffu, mx0, 1));
        mx0 = fmaxf(mx0, __shfl_xor_sync(0xffffffffu, mx0, 2));
        mx1 = fmaxf(mx1, __shfl_xor_sync(0xffffffffu, mx1, 1));
        mx1 = fmaxf(mx1, __shfl_xor_sync(0xffffffffu, mx1, 2));
        float nm0 = fmaxf(m0, mx0), nm1 = fmaxf(m1, mx1);
        float al0 = __expf(m0 - nm0), al1 = __expf(m1 - nm1);
        float s0 = 0.f, s1 = 0.f;
        #pragma unroll
        for (int j = 0; j < 8; j++) {
            S[j][0] = __expf(S[j][0] - nm0); s0 += S[j][0];
            S[j][1] = __expf(S[j][1] - nm0); s0 += S[j][1];
            S[j][2] = __expf(S[j][2] - nm1); s1 += S[j][2];
            S[j][3] = __expf(S[j][3] - nm1); s1 += S[j][3];
        }
        s0 += __shfl_xor_sync(0xffffffffu, s0, 1);
        s0 += __shfl_xor_sync(0xffffffffu, s0, 2);
        s1 += __shfl_xor_sync(0xffffffffu, s1, 1);
        s1 += __shfl_xor_sync(0xffffffffu, s1, 2);
        l0 = l0 * al0 + s0;
        l1 = l1 * al1 + s1;
        m0 = nm0; m1 = nm1;
        // skip O-rescale when max unchanged across the whole warp (common case)
        if (!__all_sync(0xffffffffu, (al0 == 1.f) & (al1 == 1.f))) {
            #pragma unroll
            for (int j = 0; j < 8; j++) {
                O[j][0] *= al0; O[j][1] *= al0;
                O[j][2] *= al1; O[j][3] *= al1;
            }
        }

        #pragma unroll
        for (int t = 0; t < 4; t++) {
            uint32_t ph[4];
            #pragma unroll
            for (int half = 0; half < 2; half++) {
                int j = 2 * t + half;
                ph[half * 2 + 0] = pack_h2(S[j][0], S[j][1]);
                ph[half * 2 + 1] = pack_h2(S[j][2], S[j][3]);
            }
            #pragma unroll
            for (int jp = 0; jp < 4; jp++) {
                uint32_t v0, v1, v2, v3;
                uint32_t off = SWZ128((t * 16 + v_row) * 128 + jp * 32 + v_cb);
                ldsm_x4t(v0, v1, v2, v3, stg + F_V + off);
                mma_f16(O[2 * jp + 0], ph[0], ph[1], ph[2], ph[3], v0, v1);
                mma_f16(O[2 * jp + 1], ph[0], ph[1], ph[2], ph[3], v2, v3);
            }
        }
        __syncthreads();
    }
    #undef F_LOAD

    float inv0 = 1.f / l0, inv1 = 1.f / l1;
    int r0 = b * Nn + qt * 128 + wm + (lid >> 2);
    int r1 = r0 + 8;
    int cb = h * 64 + (lid & 3) * 2;
    #pragma unroll
    for (int j = 0; j < 8; j++) {
        int col = cb + j * 8;
        *(uint32_t*)(oh + (size_t)r0 * Ww + col) = pack_h2(O[j][0] * inv0, O[j][1] * inv0);
        *(uint32_t*)(oh + (size_t)r1 * Ww + col) = pack_h2(O[j][2] * inv1, O[j][3] * inv1);
    }
}

// ----------------------------------------------------------------------------
// Launcher
// ----------------------------------------------------------------------------
extern "C" void kernel_launch(void* const* d_in, const int* in_sizes, int n_in,
                              void* d_out, int out_size) {
    const float* x      = (const float*)d_in[0];
    const float* ln1_g  = (const float*)d_in[1];
    const float* ln1_b  = (const float*)d_in[2];
    const float* qkv_w  = (const float*)d_in[3];
    const float* qkv_b  = (const float*)d_in[4];
    const float* proj_w = (const float*)d_in[5];
    const float* proj_b = (const float*)d_in[6];
    const float* ln2_g  = (const float*)d_in[7];
    const float* ln2_b  = (const float*)d_in[8];
    const float* fc_w   = (const float*)d_in[9];
    const float* fc_b   = (const float*)d_in[10];
    const float* fc2_w  = (const float*)d_in[11];
    const float* fc2_b  = (const float*)d_in[12];
    float* out = (float*)d_out;

    float* x1;
    __half *ah, *qh, *ath, *hh, *bh;
    cudaGetSymbolAddress((void**)&x1,  g_x1);
    cudaGetSymbolAddress((void**)&ah,  g_ah);
    cudaGetSymbolAddress((void**)&qh,  g_qh);
    cudaGetSymbolAddress((void**)&ath, g_ath);
    cudaGetSymbolAddress((void**)&hh,  g_hh);
    cudaGetSymbolAddress((void**)&bh,  g_bh);

    cudaFuncSetAttribute(tc_gemm<2>, cudaFuncAttributeMaxDynamicSharedMemorySize, GS_TOTAL);
    cudaFuncSetAttribute(tc_gemm<3>, cudaFuncAttributeMaxDynamicSharedMemorySize, GS_TOTAL);
    cudaFuncSetAttribute(tc_gemm<4>, cudaFuncAttributeMaxDynamicSharedMemorySize, GS_TOTAL);
    cudaFuncSetAttribute(flash_tc, cudaFuncAttributeMaxDynamicSharedMemorySize, F_TOTAL);

    ln_kernel<<<ROWS, 256>>>(x, ln1_g, ln1_b, ah);
    convT_kernel<<<dim3(3 * Ww / 32, Ww / 32), dim3(32, 8)>>>(qkv_w, bh, Ww, 3 * Ww);
    tc_gemm<3><<<dim3(3 * Ww / 128, ROWS / 128), 256, GS_TOTAL>>>(
        ah, bh, qkv_b, nullptr, nullptr, qh, ROWS, 3 * Ww, Ww);
    flash_tc<<<dim3(Nn / 128, Hh, Bb), 256, F_TOTAL>>>(qh, ath);
    convT_kernel<<<dim3(Ww / 32, Ww / 32), dim3(32, 8)>>>(proj_w, bh, Ww, Ww);
    tc_gemm<2><<<dim3(Ww / 128, ROWS / 128), 256, GS_TOTAL>>>(
        ath, bh, proj_b, x, x1, nullptr, ROWS, Ww, Ww);
    ln_kernel<<<ROWS, 256>>>(x1, ln2_g, ln2_b, ah);
    convT_kernel<<<dim3(4 * Ww / 32, Ww / 32), dim3(32, 8)>>>(fc_w, bh, Ww, 4 * Ww);
    tc_gemm<4><<<dim3(4 * Ww / 128, ROWS / 128), 256, GS_TOTAL>>>(
        ah, bh, fc_b, nullptr, nullptr, hh, ROWS, 4 * Ww, Ww);
    convT_kernel<<<dim3(Ww / 32, 4 * Ww / 32), dim3(32, 8)>>>(fc2_w, bh, 4 * Ww, Ww);
    tc_gemm<2><<<dim3(Ww / 128, ROWS / 128), 256, GS_TOTAL>>>(
        hh, bh, fc2_b, x1, out, nullptr, ROWS, Ww, 4 * Ww);
}